// round 2
// baseline (speedup 1.0000x reference)
#include <cuda_runtime.h>
#include <cstdint>
#include <cstddef>

#define N_NODES 100000
#define N_EDGES 100000
#define NNZ     3200000
#define D_IN    512
#define D_HID   16
#define N_CLS   7

// ---------------- scratch (device globals; no allocation allowed) ----------
__device__ float g_h[N_NODES * D_HID];      // layer1 node features h = X@W1
__device__ float g_h2[N_NODES * 8];         // layer2 node features (padded stride 8)
__device__ float g_e[N_EDGES * D_HID];      // layer1 edge features
__device__ float g_e2[N_EDGES * 8];         // layer2 edge features (padded stride 8)
__device__ float g_uexp[N_NODES];           // exp(lrelu(h . a1)) per node
__device__ float g_t1[N_NODES];             // h . a2[:D] per node
__device__ float g_t2[N_EDGES];             // e . a2[D:] per edge
__device__ float g_w[NNZ];                  // per-nnz exp scratch
__device__ int   g_eoff[N_EDGES + 1];       // edge segment offsets (sorted edge_idx)
__device__ int   g_cnt[N_NODES];
__device__ int   g_noff[N_NODES + 1];       // node CSR offsets
__device__ int   g_cur[N_NODES];
__device__ int   g_pedge[NNZ];              // edge id, permuted into node-CSR order

__device__ __forceinline__ float lrelu(float v) { return v > 0.f ? v : 0.2f * v; }

// ---------------- GEMM1: h = X @ W1, plus uexp/t1 epilogue ----------------
// block = 128 threads, 128 nodes per block, c-chunks of 64.
// thread t: node-group ng = t>>2 (4 nodes), col-group jg = t&3 (4 cols) -> 16 acc.
__global__ void k_gemm1(const float* __restrict__ X, const float* __restrict__ W,
                        const float* __restrict__ a1, const float* __restrict__ a2lo)
{
    __shared__ float sX[128 * 65];   // pad 65: node-step 4*65=260 %32 = 4 -> conflict-free
    __shared__ float sW[64 * 16];
    const int t = threadIdx.x;
    const int nbase = blockIdx.x * 128;
    const int ng = t >> 2, jg = t & 3;

    float acc[4][4];
#pragma unroll
    for (int a = 0; a < 4; a++)
#pragma unroll
        for (int b = 0; b < 4; b++) acc[a][b] = 0.f;

    for (int ck = 0; ck < D_IN; ck += 64) {
        // load X chunk: 128 rows x 64 cols (float4, coalesced)
        for (int q = t; q < 128 * 16; q += 128) {
            int row = q >> 4, fc = q & 15;
            int n = nbase + row;
            float4 v = make_float4(0.f, 0.f, 0.f, 0.f);
            if (n < N_NODES) v = *(const float4*)(X + (size_t)n * D_IN + ck + fc * 4);
            int b = row * 65 + fc * 4;
            sX[b] = v.x; sX[b + 1] = v.y; sX[b + 2] = v.z; sX[b + 3] = v.w;
        }
        // load W chunk: 64 x 16
        for (int q = t; q < 256; q += 128) {
            float4 v = *(const float4*)(W + ck * 16 + q * 4);
            *(float4*)(sW + q * 4) = v;
        }
        __syncthreads();
#pragma unroll 16
        for (int c = 0; c < 64; c++) {
            float wr[4], xr[4];
#pragma unroll
            for (int k = 0; k < 4; k++) wr[k] = sW[c * 16 + jg * 4 + k];
#pragma unroll
            for (int k = 0; k < 4; k++) xr[k] = sX[(ng * 4 + k) * 65 + c];
#pragma unroll
            for (int a = 0; a < 4; a++)
#pragma unroll
                for (int b = 0; b < 4; b++) acc[a][b] += xr[a] * wr[b];
        }
        __syncthreads();
    }

    // stage h rows into shared (stride 17), write to global
#pragma unroll
    for (int a = 0; a < 4; a++) {
        int n = nbase + ng * 4 + a;
#pragma unroll
        for (int b = 0; b < 4; b++) {
            int j = jg * 4 + b;
            sX[(ng * 4 + a) * 17 + j] = acc[a][b];
            if (n < N_NODES) g_h[(size_t)n * D_HID + j] = acc[a][b];
        }
    }
    __syncthreads();
    // epilogue: uexp, t1 per node
    {
        int n = nbase + t;
        if (n < N_NODES) {
            float uu = 0.f, tt = 0.f;
#pragma unroll
            for (int j = 0; j < D_HID; j++) {
                float hv = sX[t * 17 + j];
                uu += hv * a1[j];
                tt += hv * a2lo[j];
            }
            g_uexp[n] = __expf(lrelu(uu));
            g_t1[n] = tt;
        }
    }
}

// ---------------- GEMM2: h2 = elu(H1) @ W2, plus uexp/t1 epilogue ---------
__global__ void k_gemm2(const float* __restrict__ H1, const float* __restrict__ W2,
                        const float* __restrict__ a1, const float* __restrict__ a2lo)
{
    int n = blockIdx.x * blockDim.x + threadIdx.x;
    if (n >= N_NODES) return;
    float x[16];
    const float4* p = (const float4*)(H1 + (size_t)n * 16);
#pragma unroll
    for (int q = 0; q < 4; q++) {
        float4 v = p[q];
        x[q * 4] = v.x; x[q * 4 + 1] = v.y; x[q * 4 + 2] = v.z; x[q * 4 + 3] = v.w;
    }
#pragma unroll
    for (int c = 0; c < 16; c++) x[c] = x[c] > 0.f ? x[c] : expm1f(x[c]);
    float uu = 0.f, tt = 0.f;
#pragma unroll
    for (int j = 0; j < N_CLS; j++) {
        float s = 0.f;
#pragma unroll
        for (int c = 0; c < 16; c++) s += x[c] * __ldg(W2 + c * N_CLS + j);
        g_h2[(size_t)n * 8 + j] = s;
        uu += s * __ldg(a1 + j);
        tt += s * __ldg(a2lo + j);
    }
    g_h2[(size_t)n * 8 + 7] = 0.f;
    g_uexp[n] = __expf(lrelu(uu));
    g_t1[n] = tt;
}

// ---------------- edge offsets: lower_bound over sorted edge_idx ----------
__global__ void k_eoff(const int* __restrict__ edge_idx)
{
    int e = blockIdx.x * blockDim.x + threadIdx.x;
    if (e >= N_EDGES) return;
    int lo = 0, hi = NNZ;
    while (lo < hi) {
        int m = (lo + hi) >> 1;
        if (__ldg(edge_idx + m) < e) lo = m + 1; else hi = m;
    }
    g_eoff[e] = lo;
    if (e == 0) g_eoff[N_EDGES] = NNZ;
}

// ---------------- node CSR build (counting sort) --------------------------
__global__ void k_zero()
{
    int n = blockIdx.x * blockDim.x + threadIdx.x;
    if (n < N_NODES) g_cnt[n] = 0;
}
__global__ void k_count(const int* __restrict__ node_idx)
{
    int i = blockIdx.x * blockDim.x + threadIdx.x;
    if (i < NNZ) atomicAdd(&g_cnt[node_idx[i]], 1);
}
__global__ void k_scan()
{
    __shared__ int sp[1024];
    const int t = threadIdx.x;
    const int CH = (N_NODES + 1023) / 1024;   // 98
    int base = t * CH;
    int s = 0;
    for (int k = 0; k < CH; k++) {
        int idx = base + k;
        if (idx < N_NODES) s += g_cnt[idx];
    }
    sp[t] = s;
    __syncthreads();
    for (int o = 1; o < 1024; o <<= 1) {
        int v = (t >= o) ? sp[t - o] : 0;
        __syncthreads();
        sp[t] += v;
        __syncthreads();
    }
    int run = (t == 0) ? 0 : sp[t - 1];
    for (int k = 0; k < CH; k++) {
        int idx = base + k;
        if (idx < N_NODES) {
            g_noff[idx] = run;
            g_cur[idx] = run;
            run += g_cnt[idx];
        }
    }
    if (t == 1023) g_noff[N_NODES] = NNZ;
}
__global__ void k_scatter(const int* __restrict__ node_idx, const int* __restrict__ edge_idx)
{
    int i = blockIdx.x * blockDim.x + threadIdx.x;
    if (i >= NNZ) return;
    int n = node_idx[i];
    int pos = atomicAdd(&g_cur[n], 1);
    g_pedge[pos] = edge_idx[i];
}

// ---------------- phase 1: node -> hyperedge (edge_idx sorted) ------------
// warp per edge. Pass A: segment sum of uexp gathers (stash in g_w).
// Pass B: transposed weighted accumulate of h rows; epilogue writes e, t2.
template <int L>
__global__ void k_phase1(const int* __restrict__ node_idx, const float* __restrict__ a2hi)
{
    constexpr int D = (L == 0) ? D_HID : N_CLS;
    constexpr int STR = (L == 0) ? 16 : 8;
    constexpr int SUB = (L == 0) ? 16 : 8;
    constexpr int NPC = 32 / SUB;
    const float* feat = (L == 0) ? g_h : g_h2;
    float* efeat = (L == 0) ? g_e : g_e2;

    int w = (blockIdx.x * blockDim.x + threadIdx.x) >> 5;
    if (w >= N_EDGES) return;
    int lane = threadIdx.x & 31;
    int s = g_eoff[w], epos = g_eoff[w + 1];

    float sum = 0.f;
    for (int i = s + lane; i < epos; i += 32) {
        float ex = g_uexp[node_idx[i]];
        g_w[i] = ex;
        sum += ex;
    }
#pragma unroll
    for (int o = 16; o; o >>= 1) sum += __shfl_xor_sync(0xffffffffu, sum, o);
    float inv = 1.f / (sum + 1e-9f);

    const int j = lane % SUB;
    const int sl = lane / SUB;
    float acc = 0.f;
    for (int t0 = s; t0 < epos; t0 += 32) {
        int i = t0 + lane;
        float wv = 0.f;
        int nd = 0;
        if (i < epos) { wv = g_w[i] * inv; nd = node_idx[i]; }
        int cnt = min(32, epos - t0);
        for (int p = 0; p < cnt; p += NPC) {
            float wp = __shfl_sync(0xffffffffu, wv, p + sl);
            int   np = __shfl_sync(0xffffffffu, nd, p + sl);
            acc += wp * feat[(size_t)np * STR + j];
        }
    }
    acc += __shfl_down_sync(0xffffffffu, acc, 16);
    if (SUB == 8) acc += __shfl_down_sync(0xffffffffu, acc, 8);

    float t2p = 0.f;
    if (lane < SUB) {
        float val = (lane < D) ? acc : 0.f;
        efeat[(size_t)w * STR + lane] = val;     // zero the pad slots too
        if (lane < D) t2p = val * a2hi[lane];
    }
#pragma unroll
    for (int o = 16; o; o >>= 1) t2p += __shfl_xor_sync(0xffffffffu, t2p, o);
    if (lane == 0) g_t2[w] = t2p;
}

// ---------------- phase 2: hyperedge -> node (CSR over nodes) -------------
// warp per node; edge ids come coalesced from g_pedge.
template <int L>
__global__ void k_phase2(float* __restrict__ outp)
{
    constexpr int D = (L == 0) ? D_HID : N_CLS;
    constexpr int STR = (L == 0) ? 16 : 8;
    constexpr int SUB = (L == 0) ? 16 : 8;
    constexpr int NPC = 32 / SUB;
    const float* efeat = (L == 0) ? g_e : g_e2;

    int n = (blockIdx.x * blockDim.x + threadIdx.x) >> 5;
    if (n >= N_NODES) return;
    int lane = threadIdx.x & 31;
    int s = g_noff[n], e = g_noff[n + 1];
    float t1n = g_t1[n];

    float sum = 0.f;
    for (int i = s + lane; i < e; i += 32) {
        int ed = g_pedge[i];
        float v = lrelu(t1n + g_t2[ed]);
        float ex = __expf(v);
        g_w[i] = ex;
        sum += ex;
    }
#pragma unroll
    for (int o = 16; o; o >>= 1) sum += __shfl_xor_sync(0xffffffffu, sum, o);
    float inv = 1.f / (sum + 1e-9f);

    const int j = lane % SUB;
    const int sl = lane / SUB;
    float acc = 0.f;
    for (int t0 = s; t0 < e; t0 += 32) {
        int i = t0 + lane;
        float wv = 0.f;
        int ed = 0;
        if (i < e) { wv = g_w[i] * inv; ed = g_pedge[i]; }
        int cnt = min(32, e - t0);
        for (int p = 0; p < cnt; p += NPC) {
            float wp = __shfl_sync(0xffffffffu, wv, p + sl);
            int   ep = __shfl_sync(0xffffffffu, ed, p + sl);
            acc += wp * efeat[(size_t)ep * STR + j];
        }
    }
    acc += __shfl_down_sync(0xffffffffu, acc, 16);
    if (SUB == 8) acc += __shfl_down_sync(0xffffffffu, acc, 8);
    if (lane < D) outp[(size_t)n * D + lane] = acc;
}

// ---------------- final log_softmax over H2 rows --------------------------
__global__ void k_lsm(const float* __restrict__ H2, float* __restrict__ logp)
{
    int n = blockIdx.x * blockDim.x + threadIdx.x;
    if (n >= N_NODES) return;
    float v[N_CLS];
    float m = -1e30f;
#pragma unroll
    for (int j = 0; j < N_CLS; j++) { v[j] = H2[(size_t)n * N_CLS + j]; m = fmaxf(m, v[j]); }
    float s = 0.f;
#pragma unroll
    for (int j = 0; j < N_CLS; j++) s += __expf(v[j] - m);
    float ls = m + __logf(s);
#pragma unroll
    for (int j = 0; j < N_CLS; j++) logp[(size_t)n * N_CLS + j] = v[j] - ls;
}

// ---------------- launch ---------------------------------------------------
extern "C" void kernel_launch(void* const* d_in, const int* in_sizes, int n_in,
                              void* d_out, int out_size)
{
    const float* H   = (const float*)d_in[0];
    const float* W1  = (const float*)d_in[1];
    const float* a11 = (const float*)d_in[2];
    const float* a21 = (const float*)d_in[3];
    const float* W2  = (const float*)d_in[4];
    const float* a12 = (const float*)d_in[5];
    const float* a22 = (const float*)d_in[6];
    const int* node_idx = (const int*)d_in[7];
    const int* edge_idx = (const int*)d_in[8];

    float* out  = (float*)d_out;
    float* logp = out;                       // [N, 7]
    float* H1   = out + (size_t)N_NODES * N_CLS;                    // [N, 16]
    float* H2   = out + (size_t)N_NODES * (N_CLS + D_HID);          // [N, 7]

    // layer-1 node features + CSR build (independent; stream-ordered anyway)
    k_gemm1<<<(N_NODES + 127) / 128, 128>>>(H, W1, a11, a21);
    k_eoff<<<(N_EDGES + 255) / 256, 256>>>(edge_idx);
    k_zero<<<(N_NODES + 255) / 256, 256>>>();
    k_count<<<(NNZ + 255) / 256, 256>>>(node_idx);
    k_scan<<<1, 1024>>>();
    k_scatter<<<(NNZ + 255) / 256, 256>>>(node_idx, edge_idx);

    // layer 1
    k_phase1<0><<<N_EDGES / 8, 256>>>(node_idx, a21 + D_HID);
    k_phase2<0><<<N_NODES / 8, 256>>>(H1);

    // layer 2
    k_gemm2<<<(N_NODES + 255) / 256, 256>>>(H1, W2, a12, a22);
    k_phase1<1><<<N_EDGES / 8, 256>>>(node_idx, a22 + N_CLS);
    k_phase2<1><<<N_NODES / 8, 256>>>(H2);

    // output head
    k_lsm<<<(N_NODES + 255) / 256, 256>>>(H2, logp);
}

// round 3
// speedup vs baseline: 1.4139x; 1.4139x over previous
#include <cuda_runtime.h>
#include <cstdint>
#include <cstddef>

#define N_NODES 100000
#define N_EDGES 100000
#define NNZ     3200000
#define D_IN    512
#define D_HID   16
#define N_CLS   7

// ---------------- scratch (device globals; no allocation allowed) ----------
__device__ float g_h[N_NODES * D_HID];      // layer1 node features h = X@W1
__device__ float g_h2[N_NODES * 8];         // layer2 node features (padded stride 8)
__device__ float g_e[N_EDGES * D_HID];      // layer1 edge features
__device__ float g_e2[N_EDGES * 8];         // layer2 edge features (padded stride 8)
__device__ float g_uexp[N_NODES];           // exp(lrelu(h . a1)) per node
__device__ float g_t1[N_NODES];             // h . a2[:D] per node
__device__ float g_t2[N_EDGES];             // e . a2[D:] per edge
__device__ int   g_eoff[N_EDGES + 1];       // edge segment offsets (sorted edge_idx)
__device__ int   g_cnt[N_NODES];
__device__ int   g_noff[N_NODES + 1];       // node CSR offsets
__device__ int   g_cur[N_NODES];
__device__ int   g_pedge[NNZ];              // edge id, permuted into node-CSR order
__device__ int   g_bsum[128];
__device__ int   g_bpre[128];

__device__ __forceinline__ float lrelu(float v) { return v > 0.f ? v : 0.2f * v; }

// ---------------- GEMM1: h = X @ W1, plus uexp/t1 epilogue ----------------
__global__ void k_gemm1(const float* __restrict__ X, const float* __restrict__ W,
                        const float* __restrict__ a1, const float* __restrict__ a2lo)
{
    __shared__ float sX[128 * 65];
    __shared__ float sW[64 * 16];
    const int t = threadIdx.x;
    const int nbase = blockIdx.x * 128;
    const int ng = t >> 2, jg = t & 3;

    float acc[4][4];
#pragma unroll
    for (int a = 0; a < 4; a++)
#pragma unroll
        for (int b = 0; b < 4; b++) acc[a][b] = 0.f;

    for (int ck = 0; ck < D_IN; ck += 64) {
        for (int q = t; q < 128 * 16; q += 128) {
            int row = q >> 4, fc = q & 15;
            int n = nbase + row;
            float4 v = make_float4(0.f, 0.f, 0.f, 0.f);
            if (n < N_NODES) v = *(const float4*)(X + (size_t)n * D_IN + ck + fc * 4);
            int b = row * 65 + fc * 4;
            sX[b] = v.x; sX[b + 1] = v.y; sX[b + 2] = v.z; sX[b + 3] = v.w;
        }
        for (int q = t; q < 256; q += 128) {
            float4 v = *(const float4*)(W + ck * 16 + q * 4);
            *(float4*)(sW + q * 4) = v;
        }
        __syncthreads();
#pragma unroll 16
        for (int c = 0; c < 64; c++) {
            float wr[4], xr[4];
#pragma unroll
            for (int k = 0; k < 4; k++) wr[k] = sW[c * 16 + jg * 4 + k];
#pragma unroll
            for (int k = 0; k < 4; k++) xr[k] = sX[(ng * 4 + k) * 65 + c];
#pragma unroll
            for (int a = 0; a < 4; a++)
#pragma unroll
                for (int b = 0; b < 4; b++) acc[a][b] += xr[a] * wr[b];
        }
        __syncthreads();
    }

#pragma unroll
    for (int a = 0; a < 4; a++) {
        int n = nbase + ng * 4 + a;
#pragma unroll
        for (int b = 0; b < 4; b++) {
            int j = jg * 4 + b;
            sX[(ng * 4 + a) * 17 + j] = acc[a][b];
            if (n < N_NODES) g_h[(size_t)n * D_HID + j] = acc[a][b];
        }
    }
    __syncthreads();
    {
        int n = nbase + t;
        if (n < N_NODES) {
            float uu = 0.f, tt = 0.f;
#pragma unroll
            for (int j = 0; j < D_HID; j++) {
                float hv = sX[t * 17 + j];
                uu += hv * __ldg(a1 + j);
                tt += hv * __ldg(a2lo + j);
            }
            g_uexp[n] = __expf(lrelu(uu));
            g_t1[n] = tt;
        }
    }
}

// ---------------- prep: zero counts + edge offsets (N_NODES==N_EDGES) ------
__global__ void k_prep(const int* __restrict__ edge_idx)
{
    int e = blockIdx.x * blockDim.x + threadIdx.x;
    if (e >= N_EDGES) return;
    g_cnt[e] = 0;
    int lo = 0, hi = NNZ;
    while (lo < hi) {
        int m = (lo + hi) >> 1;
        if (__ldg(edge_idx + m) < e) lo = m + 1; else hi = m;
    }
    g_eoff[e] = lo;
    if (e == 0) g_eoff[N_EDGES] = NNZ;
}

// ---------------- node CSR build (counting sort), vectorized ---------------
__global__ void k_count(const int4* __restrict__ node_idx4)
{
    int i = blockIdx.x * blockDim.x + threadIdx.x;
    if (i >= NNZ / 4) return;
    int4 v = node_idx4[i];
    atomicAdd(&g_cnt[v.x], 1);
    atomicAdd(&g_cnt[v.y], 1);
    atomicAdd(&g_cnt[v.z], 1);
    atomicAdd(&g_cnt[v.w], 1);
}

// 100 blocks x 1000 entries: per-block exclusive scan + block total
__global__ void k_scan1()
{
    __shared__ int sp[1024];
    int t = threadIdx.x, b = blockIdx.x;
    int idx = b * 1000 + t;
    int v = (t < 1000) ? g_cnt[idx] : 0;
    sp[t] = v;
    __syncthreads();
    for (int o = 1; o < 1024; o <<= 1) {
        int u = (t >= o) ? sp[t - o] : 0;
        __syncthreads();
        sp[t] += u;
        __syncthreads();
    }
    if (t < 1000) g_noff[idx] = sp[t] - v;
    if (t == 1023) g_bsum[b] = sp[1023];
}
__global__ void k_scan2()
{
    __shared__ int sp[128];
    int t = threadIdx.x;
    int v = (t < 100) ? g_bsum[t] : 0;
    sp[t] = v;
    __syncthreads();
    for (int o = 1; o < 128; o <<= 1) {
        int u = (t >= o) ? sp[t - o] : 0;
        __syncthreads();
        sp[t] += u;
        __syncthreads();
    }
    if (t < 100) g_bpre[t] = sp[t] - v;
}
__global__ void k_scan3()
{
    int t = threadIdx.x, b = blockIdx.x;
    int idx = b * 1000 + t;
    if (t < 1000) {
        int o = g_noff[idx] + g_bpre[b];
        g_noff[idx] = o;
        g_cur[idx] = o;
    }
    if (idx == 0) g_noff[N_NODES] = NNZ;
}
__global__ void k_scatter(const int4* __restrict__ node_idx4, const int4* __restrict__ edge_idx4)
{
    int i = blockIdx.x * blockDim.x + threadIdx.x;
    if (i >= NNZ / 4) return;
    int4 nd = node_idx4[i];
    int4 ed = edge_idx4[i];
    g_pedge[atomicAdd(&g_cur[nd.x], 1)] = ed.x;
    g_pedge[atomicAdd(&g_cur[nd.y], 1)] = ed.y;
    g_pedge[atomicAdd(&g_cur[nd.z], 1)] = ed.z;
    g_pedge[atomicAdd(&g_cur[nd.w], 1)] = ed.w;
}

// ---------------- phase 1: node -> hyperedge, SINGLE PASS ------------------
// warp per edge; accumulate unnormalized, scale by 1/sum at the end.
template <int L>
__global__ void k_phase1(const int* __restrict__ node_idx, const float* __restrict__ a2hi)
{
    constexpr int D = (L == 0) ? D_HID : N_CLS;
    constexpr int STR = (L == 0) ? 16 : 8;
    constexpr int SUB = (L == 0) ? 16 : 8;
    constexpr int NPC = 32 / SUB;
    const float* feat = (L == 0) ? g_h : g_h2;
    float* efeat = (L == 0) ? g_e : g_e2;

    int w = (blockIdx.x * blockDim.x + threadIdx.x) >> 5;
    if (w >= N_EDGES) return;
    int lane = threadIdx.x & 31;
    int s = g_eoff[w], epos = g_eoff[w + 1];

    const int j = lane % SUB;
    const int sl = lane / SUB;
    float sum = 0.f, acc = 0.f;
    for (int t0 = s; t0 < epos; t0 += 32) {
        int i = t0 + lane;
        float wv = 0.f;
        int nd = 0;
        if (i < epos) { nd = node_idx[i]; wv = g_uexp[nd]; sum += wv; }
        int cnt = min(32, epos - t0);
        for (int p = 0; p < cnt; p += NPC) {
            float wp = __shfl_sync(0xffffffffu, wv, p + sl);
            int   np = __shfl_sync(0xffffffffu, nd, p + sl);
            acc += wp * feat[(size_t)np * STR + j];
        }
    }
#pragma unroll
    for (int o = 16; o; o >>= 1) sum += __shfl_xor_sync(0xffffffffu, sum, o);
    float inv = 1.f / (sum + 1e-9f);

    acc += __shfl_down_sync(0xffffffffu, acc, 16);
    if (SUB == 8) acc += __shfl_down_sync(0xffffffffu, acc, 8);

    float t2p = 0.f;
    if (lane < SUB) {
        float val = (lane < D) ? acc * inv : 0.f;
        efeat[(size_t)w * STR + lane] = val;
        if (lane < D) t2p = val * __ldg(a2hi + lane);
    }
#pragma unroll
    for (int o = 16; o; o >>= 1) t2p += __shfl_xor_sync(0xffffffffu, t2p, o);
    if (lane == 0) g_t2[w] = t2p;
}

// ---------------- phase 2 (layer 1) + fused gemm2 epilogue -----------------
__global__ void k_phase2_l1(float* __restrict__ H1out, const float* __restrict__ W2,
                            const float* __restrict__ a1, const float* __restrict__ a2lo)
{
    constexpr int STR = 16, SUB = 16, NPC = 2;

    int n = (blockIdx.x * blockDim.x + threadIdx.x) >> 5;
    if (n >= N_NODES) return;
    int lane = threadIdx.x & 31;
    int s = g_noff[n], e = g_noff[n + 1];
    float t1n = g_t1[n];

    const int j = lane % SUB;
    const int sl = lane / SUB;
    float sum = 0.f, acc = 0.f;
    for (int t0 = s; t0 < e; t0 += 32) {
        int i = t0 + lane;
        float wv = 0.f;
        int ed = 0;
        if (i < e) {
            ed = g_pedge[i];
            wv = __expf(lrelu(t1n + g_t2[ed]));
            sum += wv;
        }
        int cnt = min(32, e - t0);
        for (int p = 0; p < cnt; p += NPC) {
            float wp = __shfl_sync(0xffffffffu, wv, p + sl);
            int   ep = __shfl_sync(0xffffffffu, ed, p + sl);
            acc += wp * g_e[(size_t)ep * STR + j];
        }
    }
#pragma unroll
    for (int o = 16; o; o >>= 1) sum += __shfl_xor_sync(0xffffffffu, sum, o);
    float inv = 1.f / (sum + 1e-9f);
    acc += __shfl_down_sync(0xffffffffu, acc, 16);

    // lanes 0..15 now hold H1[n][lane]
    float h1 = acc * inv;
    if (lane < 16) H1out[(size_t)n * 16 + lane] = h1;

    // fused gemm2: h2 = elu(h1) @ W2, plus uexp/t1 for layer 2
    float x = 0.f;
    float w2r[N_CLS];
    if (lane < 16) {
        x = h1 > 0.f ? h1 : expm1f(h1);
#pragma unroll
        for (int jj = 0; jj < N_CLS; jj++) w2r[jj] = __ldg(W2 + lane * N_CLS + jj);
    } else {
#pragma unroll
        for (int jj = 0; jj < N_CLS; jj++) w2r[jj] = 0.f;
    }
    float sarr[N_CLS];
#pragma unroll
    for (int jj = 0; jj < N_CLS; jj++) {
        float p = x * w2r[jj];
        p += __shfl_xor_sync(0xffffffffu, p, 8);
        p += __shfl_xor_sync(0xffffffffu, p, 4);
        p += __shfl_xor_sync(0xffffffffu, p, 2);
        p += __shfl_xor_sync(0xffffffffu, p, 1);
        sarr[jj] = p;   // sum over lanes 0..15, valid in lanes 0..15
    }
    if (lane < N_CLS) g_h2[(size_t)n * 8 + lane] = sarr[lane];
    if (lane == 7) g_h2[(size_t)n * 8 + 7] = 0.f;
    if (lane == 0) {
        float uu = 0.f, tt = 0.f;
#pragma unroll
        for (int jj = 0; jj < N_CLS; jj++) {
            uu += sarr[jj] * __ldg(a1 + jj);
            tt += sarr[jj] * __ldg(a2lo + jj);
        }
        g_uexp[n] = __expf(lrelu(uu));
        g_t1[n] = tt;
    }
}

// ---------------- phase 2 (layer 2) + fused log_softmax --------------------
__global__ void k_phase2_l2(float* __restrict__ H2out, float* __restrict__ logp)
{
    constexpr int STR = 8, SUB = 8, NPC = 4;

    int n = (blockIdx.x * blockDim.x + threadIdx.x) >> 5;
    if (n >= N_NODES) return;
    int lane = threadIdx.x & 31;
    int s = g_noff[n], e = g_noff[n + 1];
    float t1n = g_t1[n];

    const int j = lane % SUB;
    const int sl = lane / SUB;
    float sum = 0.f, acc = 0.f;
    for (int t0 = s; t0 < e; t0 += 32) {
        int i = t0 + lane;
        float wv = 0.f;
        int ed = 0;
        if (i < e) {
            ed = g_pedge[i];
            wv = __expf(lrelu(t1n + g_t2[ed]));
            sum += wv;
        }
        int cnt = min(32, e - t0);
        for (int p = 0; p < cnt; p += NPC) {
            float wp = __shfl_sync(0xffffffffu, wv, p + sl);
            int   ep = __shfl_sync(0xffffffffu, ed, p + sl);
            acc += wp * g_e2[(size_t)ep * STR + j];
        }
    }
#pragma unroll
    for (int o = 16; o; o >>= 1) sum += __shfl_xor_sync(0xffffffffu, sum, o);
    float inv = 1.f / (sum + 1e-9f);
    acc += __shfl_down_sync(0xffffffffu, acc, 16);
    acc += __shfl_down_sync(0xffffffffu, acc, 8);

    // lanes 0..6 hold H2[n][lane]
    float v = (lane < N_CLS) ? acc * inv : -1e30f;
    if (lane < N_CLS) H2out[(size_t)n * N_CLS + lane] = v;

    // fused log_softmax over the 8-lane group (lane 7 = -inf pad)
    float m = v;
    m = fmaxf(m, __shfl_xor_sync(0xffffffffu, m, 4));
    m = fmaxf(m, __shfl_xor_sync(0xffffffffu, m, 2));
    m = fmaxf(m, __shfl_xor_sync(0xffffffffu, m, 1));
    float ex = (lane < N_CLS) ? __expf(v - m) : 0.f;
    ex += __shfl_xor_sync(0xffffffffu, ex, 4);
    ex += __shfl_xor_sync(0xffffffffu, ex, 2);
    ex += __shfl_xor_sync(0xffffffffu, ex, 1);
    float ls = m + __logf(ex);
    if (lane < N_CLS) logp[(size_t)n * N_CLS + lane] = v - ls;
}

// ---------------- launch ---------------------------------------------------
extern "C" void kernel_launch(void* const* d_in, const int* in_sizes, int n_in,
                              void* d_out, int out_size)
{
    const float* H   = (const float*)d_in[0];
    const float* W1  = (const float*)d_in[1];
    const float* a11 = (const float*)d_in[2];
    const float* a21 = (const float*)d_in[3];
    const float* W2  = (const float*)d_in[4];
    const float* a12 = (const float*)d_in[5];
    const float* a22 = (const float*)d_in[6];
    const int* node_idx = (const int*)d_in[7];
    const int* edge_idx = (const int*)d_in[8];

    float* out  = (float*)d_out;
    float* logp = out;                                              // [N, 7]
    float* H1   = out + (size_t)N_NODES * N_CLS;                    // [N, 16]
    float* H2   = out + (size_t)N_NODES * (N_CLS + D_HID);          // [N, 7]

    // CSR / segment prep
    k_prep<<<(N_EDGES + 255) / 256, 256>>>(edge_idx);
    k_count<<<(NNZ / 4 + 255) / 256, 256>>>((const int4*)node_idx);
    k_scan1<<<100, 1024>>>();
    k_scan2<<<1, 128>>>();
    k_scan3<<<100, 1024>>>();
    k_scatter<<<(NNZ / 4 + 255) / 256, 256>>>((const int4*)node_idx, (const int4*)edge_idx);

    // layer-1 node features
    k_gemm1<<<(N_NODES + 127) / 128, 128>>>(H, W1, a11, a21);

    // layer 1
    k_phase1<0><<<N_EDGES / 8, 256>>>(node_idx, a21 + D_HID);
    k_phase2_l1<<<N_NODES / 8, 256>>>(H1, W2, a12, a22);

    // layer 2
    k_phase1<1><<<N_EDGES / 8, 256>>>(node_idx, a22 + N_CLS);
    k_phase2_l2<<<N_NODES / 8, 256>>>(H2, logp);
}

// round 4
// speedup vs baseline: 1.4559x; 1.0297x over previous
#include <cuda_runtime.h>
#include <cstdint>
#include <cstddef>

#define N_NODES 100000
#define N_EDGES 100000
#define NNZ     3200000
#define D_IN    512
#define D_HID   16
#define N_CLS   7

// ---------------- scratch (device globals; no allocation allowed) ----------
__device__ float g_h[N_NODES * D_HID];      // layer1 node features h = X@W1
__device__ float g_h2[N_NODES * 8];         // layer2 node features (padded stride 8)
__device__ float g_e[N_EDGES * D_HID];      // layer1 edge features
__device__ float g_e2[N_EDGES * 8];         // layer2 edge features (padded stride 8)
__device__ float g_uexp[N_NODES];           // exp(lrelu(h . a1)) per node
__device__ float g_t1[N_NODES];             // h . a2[:D] per node
__device__ float g_t2[N_EDGES];             // e . a2[D:] per edge
__device__ int   g_eoff[N_EDGES + 1];       // edge segment offsets (sorted edge_idx)
__device__ int   g_cnt[N_NODES];
__device__ int   g_noff[N_NODES + 1];       // node CSR offsets
__device__ int   g_cur[N_NODES];
__device__ int   g_pedge[NNZ];              // edge id, permuted into node-CSR order
__device__ int   g_bsum[128];
__device__ int   g_bpre[128];

__device__ __forceinline__ float lrelu(float v) { return v > 0.f ? v : 0.2f * v; }

// ---- packed f32x2 helpers (FFMA2: 2 fp32 FMAs per instruction) ------------
__device__ __forceinline__ unsigned long long splat2(float x) {
    unsigned long long r;
    unsigned int u = __float_as_uint(x);
    asm("mov.b64 %0, {%1, %1};" : "=l"(r) : "r"(u));
    return r;
}
__device__ __forceinline__ unsigned long long ffma2(unsigned long long a,
                                                    unsigned long long b,
                                                    unsigned long long c) {
    unsigned long long d;
    asm("fma.rn.f32x2 %0, %1, %2, %3;" : "=l"(d) : "l"(a), "l"(b), "l"(c));
    return d;
}
__device__ __forceinline__ void unpack2(unsigned long long v, float& lo, float& hi) {
    unsigned int a, b;
    asm("mov.b64 {%0, %1}, %2;" : "=r"(a), "=r"(b) : "l"(v));
    lo = __uint_as_float(a);
    hi = __uint_as_float(b);
}

// ---------------- GEMM1: h = X @ W1 (FFMA2), plus uexp/t1 epilogue --------
// block = 128 threads, 128 nodes per block, c-chunks of 64.
// thread t: node-group ng = t>>2 (4 nodes), col-group jg = t&3 (4 cols,
// as 2 f32x2 column-pairs) -> 8 packed accumulators.
__global__ void k_gemm1(const float* __restrict__ X, const float* __restrict__ W,
                        const float* __restrict__ a1, const float* __restrict__ a2lo)
{
    __shared__ __align__(16) float sX[128 * 65];
    __shared__ __align__(16) float sW[64 * 16];
    const int t = threadIdx.x;
    const int nbase = blockIdx.x * 128;
    const int ng = t >> 2, jg = t & 3;

    unsigned long long acc[4][2];
#pragma unroll
    for (int a = 0; a < 4; a++) { acc[a][0] = 0ull; acc[a][1] = 0ull; }

    for (int ck = 0; ck < D_IN; ck += 64) {
        for (int q = t; q < 128 * 16; q += 128) {
            int row = q >> 4, fc = q & 15;
            int n = nbase + row;
            float4 v = make_float4(0.f, 0.f, 0.f, 0.f);
            if (n < N_NODES) v = *(const float4*)(X + (size_t)n * D_IN + ck + fc * 4);
            int b = row * 65 + fc * 4;
            sX[b] = v.x; sX[b + 1] = v.y; sX[b + 2] = v.z; sX[b + 3] = v.w;
        }
        for (int q = t; q < 256; q += 128) {
            float4 v = *(const float4*)(W + ck * 16 + q * 4);
            *(float4*)(sW + q * 4) = v;
        }
        __syncthreads();
#pragma unroll 16
        for (int c = 0; c < 64; c++) {
            // two column-pairs of W row c (8-byte aligned: jg*4 is even)
            unsigned long long wp0 = *(const unsigned long long*)(sW + c * 16 + jg * 4);
            unsigned long long wp1 = *(const unsigned long long*)(sW + c * 16 + jg * 4 + 2);
#pragma unroll
            for (int a = 0; a < 4; a++) {
                unsigned long long xs = splat2(sX[(ng * 4 + a) * 65 + c]);
                acc[a][0] = ffma2(xs, wp0, acc[a][0]);
                acc[a][1] = ffma2(xs, wp1, acc[a][1]);
            }
        }
        __syncthreads();
    }

#pragma unroll
    for (int a = 0; a < 4; a++) {
        int n = nbase + ng * 4 + a;
        float v0, v1, v2, v3;
        unpack2(acc[a][0], v0, v1);
        unpack2(acc[a][1], v2, v3);
        int j = jg * 4;
        int srow = (ng * 4 + a) * 17;
        sX[srow + j] = v0; sX[srow + j + 1] = v1;
        sX[srow + j + 2] = v2; sX[srow + j + 3] = v3;
        if (n < N_NODES)
            *(float4*)(g_h + (size_t)n * D_HID + j) = make_float4(v0, v1, v2, v3);
    }
    __syncthreads();
    {
        int n = nbase + t;
        if (n < N_NODES) {
            float uu = 0.f, tt = 0.f;
#pragma unroll
            for (int j = 0; j < D_HID; j++) {
                float hv = sX[t * 17 + j];
                uu += hv * __ldg(a1 + j);
                tt += hv * __ldg(a2lo + j);
            }
            g_uexp[n] = __expf(lrelu(uu));
            g_t1[n] = tt;
        }
    }
}

// ---------------- edge offsets: lower_bound over sorted edge_idx ----------
__global__ void k_eoff(const int* __restrict__ edge_idx)
{
    int e = blockIdx.x * blockDim.x + threadIdx.x;
    if (e >= N_EDGES) return;
    int lo = 0, hi = NNZ;
    while (lo < hi) {
        int m = (lo + hi) >> 1;
        if (__ldg(edge_idx + m) < e) lo = m + 1; else hi = m;
    }
    g_eoff[e] = lo;
    if (e == 0) g_eoff[N_EDGES] = NNZ;
}

// ---------------- node CSR build (counting sort), vectorized ---------------
__global__ void k_count(const int4* __restrict__ node_idx4)
{
    int i = blockIdx.x * blockDim.x + threadIdx.x;
    if (i >= NNZ / 4) return;
    int4 v = node_idx4[i];
    atomicAdd(&g_cnt[v.x], 1);
    atomicAdd(&g_cnt[v.y], 1);
    atomicAdd(&g_cnt[v.z], 1);
    atomicAdd(&g_cnt[v.w], 1);
}

// 100 blocks x 1000 entries: per-block exclusive scan + block total
__global__ void k_scan1()
{
    __shared__ int sp[1024];
    int t = threadIdx.x, b = blockIdx.x;
    int idx = b * 1000 + t;
    int v = (t < 1000) ? g_cnt[idx] : 0;
    sp[t] = v;
    __syncthreads();
    for (int o = 1; o < 1024; o <<= 1) {
        int u = (t >= o) ? sp[t - o] : 0;
        __syncthreads();
        sp[t] += u;
        __syncthreads();
    }
    if (t < 1000) g_noff[idx] = sp[t] - v;
    if (t == 1023) g_bsum[b] = sp[1023];
}
__global__ void k_scan2()
{
    __shared__ int sp[128];
    int t = threadIdx.x;
    int v = (t < 100) ? g_bsum[t] : 0;
    sp[t] = v;
    __syncthreads();
    for (int o = 1; o < 128; o <<= 1) {
        int u = (t >= o) ? sp[t - o] : 0;
        __syncthreads();
        sp[t] += u;
        __syncthreads();
    }
    if (t < 100) g_bpre[t] = sp[t] - v;
}
__global__ void k_scan3()
{
    int t = threadIdx.x, b = blockIdx.x;
    int idx = b * 1000 + t;
    if (t < 1000) {
        int o = g_noff[idx] + g_bpre[b];
        g_noff[idx] = o;
        g_cur[idx] = o;
    }
    if (idx == 0) g_noff[N_NODES] = NNZ;
}
__global__ void k_scatter(const int4* __restrict__ node_idx4, const int4* __restrict__ edge_idx4)
{
    int i = blockIdx.x * blockDim.x + threadIdx.x;
    if (i >= NNZ / 4) return;
    int4 nd = node_idx4[i];
    int4 ed = edge_idx4[i];
    g_pedge[atomicAdd(&g_cur[nd.x], 1)] = ed.x;
    g_pedge[atomicAdd(&g_cur[nd.y], 1)] = ed.y;
    g_pedge[atomicAdd(&g_cur[nd.z], 1)] = ed.z;
    g_pedge[atomicAdd(&g_cur[nd.w], 1)] = ed.w;
}

// ---------------- phase 1: node -> hyperedge, SINGLE PASS ------------------
template <int L>
__global__ void k_phase1(const int* __restrict__ node_idx, const float* __restrict__ a2hi)
{
    constexpr int D = (L == 0) ? D_HID : N_CLS;
    constexpr int STR = (L == 0) ? 16 : 8;
    constexpr int SUB = (L == 0) ? 16 : 8;
    constexpr int NPC = 32 / SUB;
    const float* feat = (L == 0) ? g_h : g_h2;
    float* efeat = (L == 0) ? g_e : g_e2;

    int w = (blockIdx.x * blockDim.x + threadIdx.x) >> 5;
    if (w >= N_EDGES) return;
    int lane = threadIdx.x & 31;
    int s = g_eoff[w], epos = g_eoff[w + 1];

    const int j = lane % SUB;
    const int sl = lane / SUB;
    float sum = 0.f, acc = 0.f;
    for (int t0 = s; t0 < epos; t0 += 32) {
        int i = t0 + lane;
        float wv = 0.f;
        int nd = 0;
        if (i < epos) { nd = node_idx[i]; wv = g_uexp[nd]; sum += wv; }
        int cnt = min(32, epos - t0);
        for (int p = 0; p < cnt; p += NPC) {
            float wp = __shfl_sync(0xffffffffu, wv, p + sl);
            int   np = __shfl_sync(0xffffffffu, nd, p + sl);
            acc += wp * feat[(size_t)np * STR + j];
        }
    }
#pragma unroll
    for (int o = 16; o; o >>= 1) sum += __shfl_xor_sync(0xffffffffu, sum, o);
    float inv = 1.f / (sum + 1e-9f);

    acc += __shfl_down_sync(0xffffffffu, acc, 16);
    if (SUB == 8) acc += __shfl_down_sync(0xffffffffu, acc, 8);

    float t2p = 0.f;
    if (lane < SUB) {
        float val = (lane < D) ? acc * inv : 0.f;
        efeat[(size_t)w * STR + lane] = val;
        if (lane < D) t2p = val * __ldg(a2hi + lane);
    }
#pragma unroll
    for (int o = 16; o; o >>= 1) t2p += __shfl_xor_sync(0xffffffffu, t2p, o);
    if (lane == 0) g_t2[w] = t2p;
}

// ---------------- phase 2 (layer 1) + fused gemm2 epilogue -----------------
__global__ void k_phase2_l1(float* __restrict__ H1out, const float* __restrict__ W2,
                            const float* __restrict__ a1, const float* __restrict__ a2lo)
{
    constexpr int STR = 16, SUB = 16, NPC = 2;

    int n = (blockIdx.x * blockDim.x + threadIdx.x) >> 5;
    if (n >= N_NODES) return;
    int lane = threadIdx.x & 31;
    int s = g_noff[n], e = g_noff[n + 1];
    float t1n = g_t1[n];

    const int j = lane % SUB;
    const int sl = lane / SUB;
    float sum = 0.f, acc = 0.f;
    for (int t0 = s; t0 < e; t0 += 32) {
        int i = t0 + lane;
        float wv = 0.f;
        int ed = 0;
        if (i < e) {
            ed = g_pedge[i];
            wv = __expf(lrelu(t1n + g_t2[ed]));
            sum += wv;
        }
        int cnt = min(32, e - t0);
        for (int p = 0; p < cnt; p += NPC) {
            float wp = __shfl_sync(0xffffffffu, wv, p + sl);
            int   ep = __shfl_sync(0xffffffffu, ed, p + sl);
            acc += wp * g_e[(size_t)ep * STR + j];
        }
    }
#pragma unroll
    for (int o = 16; o; o >>= 1) sum += __shfl_xor_sync(0xffffffffu, sum, o);
    float inv = 1.f / (sum + 1e-9f);
    acc += __shfl_down_sync(0xffffffffu, acc, 16);

    // lanes 0..15 now hold H1[n][lane]
    float h1 = acc * inv;
    if (lane < 16) H1out[(size_t)n * 16 + lane] = h1;

    // fused gemm2: h2 = elu(h1) @ W2, plus uexp/t1 for layer 2
    float x = 0.f;
    float w2r[N_CLS];
    if (lane < 16) {
        x = h1 > 0.f ? h1 : expm1f(h1);
#pragma unroll
        for (int jj = 0; jj < N_CLS; jj++) w2r[jj] = __ldg(W2 + lane * N_CLS + jj);
    } else {
#pragma unroll
        for (int jj = 0; jj < N_CLS; jj++) w2r[jj] = 0.f;
    }
    float sarr[N_CLS];
#pragma unroll
    for (int jj = 0; jj < N_CLS; jj++) {
        float p = x * w2r[jj];
        p += __shfl_xor_sync(0xffffffffu, p, 8);
        p += __shfl_xor_sync(0xffffffffu, p, 4);
        p += __shfl_xor_sync(0xffffffffu, p, 2);
        p += __shfl_xor_sync(0xffffffffu, p, 1);
        sarr[jj] = p;   // sum over lanes 0..15, valid in lanes 0..15
    }
    if (lane < N_CLS) g_h2[(size_t)n * 8 + lane] = sarr[lane];
    if (lane == 7) g_h2[(size_t)n * 8 + 7] = 0.f;
    if (lane == 0) {
        float uu = 0.f, tt = 0.f;
#pragma unroll
        for (int jj = 0; jj < N_CLS; jj++) {
            uu += sarr[jj] * __ldg(a1 + jj);
            tt += sarr[jj] * __ldg(a2lo + jj);
        }
        g_uexp[n] = __expf(lrelu(uu));
        g_t1[n] = tt;
    }
}

// ---------------- phase 2 (layer 2) + fused log_softmax --------------------
__global__ void k_phase2_l2(float* __restrict__ H2out, float* __restrict__ logp)
{
    constexpr int STR = 8, SUB = 8, NPC = 4;

    int n = (blockIdx.x * blockDim.x + threadIdx.x) >> 5;
    if (n >= N_NODES) return;
    int lane = threadIdx.x & 31;
    int s = g_noff[n], e = g_noff[n + 1];
    float t1n = g_t1[n];

    const int j = lane % SUB;
    const int sl = lane / SUB;
    float sum = 0.f, acc = 0.f;
    for (int t0 = s; t0 < e; t0 += 32) {
        int i = t0 + lane;
        float wv = 0.f;
        int ed = 0;
        if (i < e) {
            ed = g_pedge[i];
            wv = __expf(lrelu(t1n + g_t2[ed]));
            sum += wv;
        }
        int cnt = min(32, e - t0);
        for (int p = 0; p < cnt; p += NPC) {
            float wp = __shfl_sync(0xffffffffu, wv, p + sl);
            int   ep = __shfl_sync(0xffffffffu, ed, p + sl);
            acc += wp * g_e2[(size_t)ep * STR + j];
        }
    }
#pragma unroll
    for (int o = 16; o; o >>= 1) sum += __shfl_xor_sync(0xffffffffu, sum, o);
    float inv = 1.f / (sum + 1e-9f);
    acc += __shfl_down_sync(0xffffffffu, acc, 16);
    acc += __shfl_down_sync(0xffffffffu, acc, 8);

    // lanes 0..6 hold H2[n][lane]
    float v = (lane < N_CLS) ? acc * inv : -1e30f;
    if (lane < N_CLS) H2out[(size_t)n * N_CLS + lane] = v;

    // fused log_softmax over the 8-lane group (lane 7 = -inf pad)
    float m = v;
    m = fmaxf(m, __shfl_xor_sync(0xffffffffu, m, 4));
    m = fmaxf(m, __shfl_xor_sync(0xffffffffu, m, 2));
    m = fmaxf(m, __shfl_xor_sync(0xffffffffu, m, 1));
    float ex = (lane < N_CLS) ? __expf(v - m) : 0.f;
    ex += __shfl_xor_sync(0xffffffffu, ex, 4);
    ex += __shfl_xor_sync(0xffffffffu, ex, 2);
    ex += __shfl_xor_sync(0xffffffffu, ex, 1);
    float ls = m + __logf(ex);
    if (lane < N_CLS) logp[(size_t)n * N_CLS + lane] = v - ls;
}

// ---------------- launch ---------------------------------------------------
// Fork-join: CSR build (memset/count/scan/scatter) runs on a side stream,
// overlapping with eoff/gemm1/phase1<0> on the main (legacy) stream. Captured
// as parallel graph branches via event fork/join.
extern "C" void kernel_launch(void* const* d_in, const int* in_sizes, int n_in,
                              void* d_out, int out_size)
{
    const float* H   = (const float*)d_in[0];
    const float* W1  = (const float*)d_in[1];
    const float* a11 = (const float*)d_in[2];
    const float* a21 = (const float*)d_in[3];
    const float* W2  = (const float*)d_in[4];
    const float* a12 = (const float*)d_in[5];
    const float* a22 = (const float*)d_in[6];
    const int* node_idx = (const int*)d_in[7];
    const int* edge_idx = (const int*)d_in[8];

    float* out  = (float*)d_out;
    float* logp = out;                                              // [N, 7]
    float* H1   = out + (size_t)N_NODES * N_CLS;                    // [N, 16]
    float* H2   = out + (size_t)N_NODES * (N_CLS + D_HID);          // [N, 7]

    // one-time host-side resources (no device allocation; work is identical
    // on every call)
    static cudaStream_t s1 = nullptr;
    static cudaEvent_t evF = nullptr, evJ = nullptr;
    static void* cnt_ptr = nullptr;
    if (s1 == nullptr) {
        cudaStreamCreateWithFlags(&s1, cudaStreamNonBlocking);
        cudaEventCreateWithFlags(&evF, cudaEventDisableTiming);
        cudaEventCreateWithFlags(&evJ, cudaEventDisableTiming);
        cudaGetSymbolAddress(&cnt_ptr, g_cnt);
    }

    // fork
    cudaEventRecord(evF, 0);
    cudaStreamWaitEvent(s1, evF, 0);

    // main-stream chain: eoff -> gemm1 -> phase1<0>
    k_eoff<<<(N_EDGES + 255) / 256, 256>>>(edge_idx);

    // side-stream chain: CSR build
    cudaMemsetAsync(cnt_ptr, 0, N_NODES * sizeof(int), s1);
    k_count<<<(NNZ / 4 + 255) / 256, 256, 0, s1>>>((const int4*)node_idx);
    k_scan1<<<100, 1024, 0, s1>>>();
    k_scan2<<<1, 128, 0, s1>>>();
    k_scan3<<<100, 1024, 0, s1>>>();

    k_gemm1<<<(N_NODES + 127) / 128, 128>>>(H, W1, a11, a21);

    k_scatter<<<(NNZ / 4 + 255) / 256, 256, 0, s1>>>((const int4*)node_idx,
                                                     (const int4*)edge_idx);
    cudaEventRecord(evJ, s1);

    k_phase1<0><<<N_EDGES / 8, 256>>>(node_idx, a21 + D_HID);

    // join: phase2 needs the node CSR
    cudaStreamWaitEvent(0, evJ, 0);

    k_phase2_l1<<<N_NODES / 8, 256>>>(H1, W2, a12, a22);
    k_phase1<1><<<N_EDGES / 8, 256>>>(node_idx, a22 + N_CLS);
    k_phase2_l2<<<N_NODES / 8, 256>>>(H2, logp);
}

// round 5
// speedup vs baseline: 1.5537x; 1.0672x over previous
#include <cuda_runtime.h>
#include <cstdint>
#include <cstddef>

#define N_NODES 100000
#define N_EDGES 100000
#define NNZ     3200000
#define D_IN    512
#define D_HID   16
#define N_CLS   7

// ---------------- scratch (device globals; no allocation allowed) ----------
// layer1 node rows:  [0..15] = h*u, [16] = u          (stride 32 floats, 128B)
__device__ float g_hu1[(size_t)N_NODES * 32];
// layer1 edge rows:  [0..15] = e,   [16] = t2         (stride 32 floats)
__device__ float g_et1[(size_t)N_EDGES * 32];
// layer2 node rows:  [0..6] = h2*u, [7]=0, [8] = u    (stride 12 floats, 48B)
__device__ float g_hu2[(size_t)N_NODES * 12];
// layer2 edge rows:  [0..6] = e2,   [7]=0, [8] = t2   (stride 12 floats)
__device__ float g_et2[(size_t)N_EDGES * 12];
__device__ float g_t1[N_NODES];             // h . a2[:D] per node
__device__ int   g_eoff[N_EDGES + 1];       // edge segment offsets (sorted edge_idx)
__device__ int   g_cnt[N_NODES];
__device__ int   g_noff[N_NODES + 1];       // node CSR offsets
__device__ int   g_cur[N_NODES];
__device__ int   g_pedge[NNZ];              // edge id, permuted into node-CSR order
__device__ int   g_bsum[128];
__device__ int   g_bpre[128];

__device__ __forceinline__ float lrelu(float v) { return v > 0.f ? v : 0.2f * v; }

// ---- packed f32x2 helpers --------------------------------------------------
__device__ __forceinline__ unsigned long long splat2(float x) {
    unsigned long long r;
    unsigned int u = __float_as_uint(x);
    asm("mov.b64 %0, {%1, %1};" : "=l"(r) : "r"(u));
    return r;
}
__device__ __forceinline__ unsigned long long ffma2(unsigned long long a,
                                                    unsigned long long b,
                                                    unsigned long long c) {
    unsigned long long d;
    asm("fma.rn.f32x2 %0, %1, %2, %3;" : "=l"(d) : "l"(a), "l"(b), "l"(c));
    return d;
}
__device__ __forceinline__ void unpack2(unsigned long long v, float& lo, float& hi) {
    unsigned int a, b;
    asm("mov.b64 {%0, %1}, %2;" : "=r"(a), "=r"(b) : "l"(v));
    lo = __uint_as_float(a);
    hi = __uint_as_float(b);
}

// ---------------- GEMM1: h = X @ W1 (FFMA2); epilogue writes g_hu1 ---------
__global__ void k_gemm1(const float* __restrict__ X, const float* __restrict__ W,
                        const float* __restrict__ a1, const float* __restrict__ a2lo)
{
    __shared__ __align__(16) float sX[128 * 65];
    __shared__ __align__(16) float sW[64 * 16];
    const int t = threadIdx.x;
    const int nbase = blockIdx.x * 128;
    const int ng = t >> 2, jg = t & 3;

    unsigned long long acc[4][2];
#pragma unroll
    for (int a = 0; a < 4; a++) { acc[a][0] = 0ull; acc[a][1] = 0ull; }

    for (int ck = 0; ck < D_IN; ck += 64) {
        for (int q = t; q < 128 * 16; q += 128) {
            int row = q >> 4, fc = q & 15;
            int n = nbase + row;
            float4 v = make_float4(0.f, 0.f, 0.f, 0.f);
            if (n < N_NODES) v = *(const float4*)(X + (size_t)n * D_IN + ck + fc * 4);
            int b = row * 65 + fc * 4;
            sX[b] = v.x; sX[b + 1] = v.y; sX[b + 2] = v.z; sX[b + 3] = v.w;
        }
        for (int q = t; q < 256; q += 128) {
            float4 v = *(const float4*)(W + ck * 16 + q * 4);
            *(float4*)(sW + q * 4) = v;
        }
        __syncthreads();
#pragma unroll 16
        for (int c = 0; c < 64; c++) {
            unsigned long long wp0 = *(const unsigned long long*)(sW + c * 16 + jg * 4);
            unsigned long long wp1 = *(const unsigned long long*)(sW + c * 16 + jg * 4 + 2);
#pragma unroll
            for (int a = 0; a < 4; a++) {
                unsigned long long xs = splat2(sX[(ng * 4 + a) * 65 + c]);
                acc[a][0] = ffma2(xs, wp0, acc[a][0]);
                acc[a][1] = ffma2(xs, wp1, acc[a][1]);
            }
        }
        __syncthreads();
    }

#pragma unroll
    for (int a = 0; a < 4; a++) {
        float v0, v1, v2, v3;
        unpack2(acc[a][0], v0, v1);
        unpack2(acc[a][1], v2, v3);
        int j = jg * 4;
        int srow = (ng * 4 + a) * 17;
        sX[srow + j] = v0; sX[srow + j + 1] = v1;
        sX[srow + j + 2] = v2; sX[srow + j + 3] = v3;
    }
    __syncthreads();
    // epilogue: per node compute u = exp(lrelu(h.a1)), t1 = h.a2lo,
    // and write premultiplied row [h*u (16), u].
    {
        int n = nbase + t;
        if (n < N_NODES) {
            float hv[16];
            float uu = 0.f, tt = 0.f;
#pragma unroll
            for (int j = 0; j < D_HID; j++) {
                hv[j] = sX[t * 17 + j];
                uu += hv[j] * __ldg(a1 + j);
                tt += hv[j] * __ldg(a2lo + j);
            }
            float u = __expf(lrelu(uu));
            float* dst = g_hu1 + (size_t)n * 32;
#pragma unroll
            for (int q = 0; q < 4; q++)
                *(float4*)(dst + q * 4) = make_float4(hv[q * 4] * u, hv[q * 4 + 1] * u,
                                                      hv[q * 4 + 2] * u, hv[q * 4 + 3] * u);
            dst[16] = u;
            g_t1[n] = tt;
        }
    }
}

// ---------------- edge offsets: lower_bound over sorted edge_idx ----------
__global__ void k_eoff(const int* __restrict__ edge_idx)
{
    int e = blockIdx.x * blockDim.x + threadIdx.x;
    if (e >= N_EDGES) return;
    int lo = 0, hi = NNZ;
    while (lo < hi) {
        int m = (lo + hi) >> 1;
        if (__ldg(edge_idx + m) < e) lo = m + 1; else hi = m;
    }
    g_eoff[e] = lo;
    if (e == 0) g_eoff[N_EDGES] = NNZ;
}

// ---------------- node CSR build (counting sort), vectorized ---------------
__global__ void k_count(const int4* __restrict__ node_idx4)
{
    int i = blockIdx.x * blockDim.x + threadIdx.x;
    if (i >= NNZ / 4) return;
    int4 v = node_idx4[i];
    atomicAdd(&g_cnt[v.x], 1);
    atomicAdd(&g_cnt[v.y], 1);
    atomicAdd(&g_cnt[v.z], 1);
    atomicAdd(&g_cnt[v.w], 1);
}
__global__ void k_scan1()
{
    __shared__ int sp[1024];
    int t = threadIdx.x, b = blockIdx.x;
    int idx = b * 1000 + t;
    int v = (t < 1000) ? g_cnt[idx] : 0;
    sp[t] = v;
    __syncthreads();
    for (int o = 1; o < 1024; o <<= 1) {
        int u = (t >= o) ? sp[t - o] : 0;
        __syncthreads();
        sp[t] += u;
        __syncthreads();
    }
    if (t < 1000) g_noff[idx] = sp[t] - v;
    if (t == 1023) g_bsum[b] = sp[1023];
}
__global__ void k_scan2()
{
    __shared__ int sp[128];
    int t = threadIdx.x;
    int v = (t < 100) ? g_bsum[t] : 0;
    sp[t] = v;
    __syncthreads();
    for (int o = 1; o < 128; o <<= 1) {
        int u = (t >= o) ? sp[t - o] : 0;
        __syncthreads();
        sp[t] += u;
        __syncthreads();
    }
    if (t < 100) g_bpre[t] = sp[t] - v;
}
__global__ void k_scan3()
{
    int t = threadIdx.x, b = blockIdx.x;
    int idx = b * 1000 + t;
    if (t < 1000) {
        int o = g_noff[idx] + g_bpre[b];
        g_noff[idx] = o;
        g_cur[idx] = o;
    }
    if (idx == 0) g_noff[N_NODES] = NNZ;
}
__global__ void k_scatter(const int4* __restrict__ node_idx4, const int4* __restrict__ edge_idx4)
{
    int i = blockIdx.x * blockDim.x + threadIdx.x;
    if (i >= NNZ / 4) return;
    int4 nd = node_idx4[i];
    int4 ed = edge_idx4[i];
    g_pedge[atomicAdd(&g_cur[nd.x], 1)] = ed.x;
    g_pedge[atomicAdd(&g_cur[nd.y], 1)] = ed.y;
    g_pedge[atomicAdd(&g_cur[nd.z], 1)] = ed.z;
    g_pedge[atomicAdd(&g_cur[nd.w], 1)] = ed.w;
}

// ---------------- phase 1, layer 1: segmented sum of premultiplied rows ----
// warp per edge; 8 groups of 4 lanes, each group sums one row per iteration.
__global__ void k_phase1_l1(const int* __restrict__ node_idx, const float* __restrict__ a2hi)
{
    int w = (blockIdx.x * blockDim.x + threadIdx.x) >> 5;
    if (w >= N_EDGES) return;
    int lane = threadIdx.x & 31;
    const int q = lane >> 2, r = lane & 3;
    int s = g_eoff[w], epos = g_eoff[w + 1];

    float4 acc = make_float4(0.f, 0.f, 0.f, 0.f);
    float usum = 0.f;
    for (int t0 = s; t0 < epos; t0 += 32) {
#pragma unroll
        for (int k = 0; k < 4; k++) {
            int i = t0 + k * 8 + q;
            if (i < epos) {
                int nd = __ldg(node_idx + i);
                const float* row = g_hu1 + (size_t)nd * 32;
                float4 v = *(const float4*)(row + r * 4);
                acc.x += v.x; acc.y += v.y; acc.z += v.z; acc.w += v.w;
                if (r == 3) usum += __ldg(row + 16);
            }
        }
    }
    // reduce rows over the 8 groups (q): lanes 0..3 end with totals
#pragma unroll
    for (int o = 16; o >= 4; o >>= 1) {
        acc.x += __shfl_down_sync(0xffffffffu, acc.x, o);
        acc.y += __shfl_down_sync(0xffffffffu, acc.y, o);
        acc.z += __shfl_down_sync(0xffffffffu, acc.z, o);
        acc.w += __shfl_down_sync(0xffffffffu, acc.w, o);
    }
#pragma unroll
    for (int o = 16; o; o >>= 1) usum += __shfl_xor_sync(0xffffffffu, usum, o);
    float inv = 1.f / (usum + 1e-9f);

    float t2p = 0.f;
    if (lane < 4) {
        float4 val = make_float4(acc.x * inv, acc.y * inv, acc.z * inv, acc.w * inv);
        *(float4*)(g_et1 + (size_t)w * 32 + r * 4) = val;
        t2p = val.x * __ldg(a2hi + r * 4) + val.y * __ldg(a2hi + r * 4 + 1)
            + val.z * __ldg(a2hi + r * 4 + 2) + val.w * __ldg(a2hi + r * 4 + 3);
    }
    t2p += __shfl_xor_sync(0xffffffffu, t2p, 1);
    t2p += __shfl_xor_sync(0xffffffffu, t2p, 2);
    if (lane == 0) g_et1[(size_t)w * 32 + 16] = t2p;
}

// ---------------- phase 2, layer 1 + fused gemm2 epilogue ------------------
__global__ void k_phase2_l1(float* __restrict__ H1out, const float* __restrict__ W2,
                            const float* __restrict__ a1, const float* __restrict__ a2lo)
{
    int n = (blockIdx.x * blockDim.x + threadIdx.x) >> 5;
    if (n >= N_NODES) return;
    int lane = threadIdx.x & 31;
    const int q = lane >> 2, r = lane & 3;
    int s = g_noff[n], e = g_noff[n + 1];
    float t1n = g_t1[n];

    float4 acc = make_float4(0.f, 0.f, 0.f, 0.f);
    float wsum = 0.f;
    for (int t0 = s; t0 < e; t0 += 32) {
#pragma unroll
        for (int k = 0; k < 4; k++) {
            int i = t0 + k * 8 + q;
            bool act = (i < e);
            int ed = act ? __ldg(g_pedge + i) : 0;
            const float* row = g_et1 + (size_t)ed * 32;
            float4 v = make_float4(0.f, 0.f, 0.f, 0.f);
            if (act) v = *(const float4*)(row + r * 4);
            float wv = 0.f;
            if (r == 3 && act) wv = __expf(lrelu(t1n + __ldg(row + 16)));
            float wvb = __shfl_sync(0xffffffffu, wv, lane | 3);
            if (r == 3) wsum += wv;
            acc.x += wvb * v.x; acc.y += wvb * v.y;
            acc.z += wvb * v.z; acc.w += wvb * v.w;
        }
    }
#pragma unroll
    for (int o = 16; o >= 4; o >>= 1) {
        acc.x += __shfl_down_sync(0xffffffffu, acc.x, o);
        acc.y += __shfl_down_sync(0xffffffffu, acc.y, o);
        acc.z += __shfl_down_sync(0xffffffffu, acc.z, o);
        acc.w += __shfl_down_sync(0xffffffffu, acc.w, o);
    }
#pragma unroll
    for (int o = 16; o; o >>= 1) wsum += __shfl_xor_sync(0xffffffffu, wsum, o);
    float inv = 1.f / (wsum + 1e-9f);

    float4 h14 = make_float4(acc.x * inv, acc.y * inv, acc.z * inv, acc.w * inv);
    if (lane < 4) *(float4*)(H1out + (size_t)n * 16 + r * 4) = h14;

    // redistribute H1 to lanes 0..15 (lane c gets component c&3 from lane c>>2)
    float cx = __shfl_sync(0xffffffffu, h14.x, lane >> 2);
    float cy = __shfl_sync(0xffffffffu, h14.y, lane >> 2);
    float cz = __shfl_sync(0xffffffffu, h14.z, lane >> 2);
    float cw = __shfl_sync(0xffffffffu, h14.w, lane >> 2);
    int sel = lane & 3;
    float h1 = (sel == 0) ? cx : (sel == 1) ? cy : (sel == 2) ? cz : cw;

    // fused gemm2: h2 = elu(h1) @ W2, plus u/t1 for layer 2
    float x = 0.f;
    float w2r[N_CLS];
    if (lane < 16) {
        x = h1 > 0.f ? h1 : expm1f(h1);
#pragma unroll
        for (int jj = 0; jj < N_CLS; jj++) w2r[jj] = __ldg(W2 + lane * N_CLS + jj);
    } else {
#pragma unroll
        for (int jj = 0; jj < N_CLS; jj++) w2r[jj] = 0.f;
    }
    float sarr[N_CLS];
#pragma unroll
    for (int jj = 0; jj < N_CLS; jj++) {
        float p = x * w2r[jj];
        p += __shfl_xor_sync(0xffffffffu, p, 8);
        p += __shfl_xor_sync(0xffffffffu, p, 4);
        p += __shfl_xor_sync(0xffffffffu, p, 2);
        p += __shfl_xor_sync(0xffffffffu, p, 1);
        sarr[jj] = p;   // valid in lanes 0..15
    }
    float uu = 0.f, tt = 0.f;
#pragma unroll
    for (int jj = 0; jj < N_CLS; jj++) {
        uu += sarr[jj] * __ldg(a1 + jj);
        tt += sarr[jj] * __ldg(a2lo + jj);
    }
    float u = __expf(lrelu(uu));
    float* dst = g_hu2 + (size_t)n * 12;
    if (lane < N_CLS) dst[lane] = sarr[lane] * u;
    if (lane == 7) dst[7] = 0.f;
    if (lane == 0) {
        dst[8] = u;
        g_t1[n] = tt;
    }
}

// ---------------- phase 1, layer 2 -----------------------------------------
// warp per edge; 16 groups of 2 lanes, row = 8 floats (feature 7 = 0 pad).
__global__ void k_phase1_l2(const int* __restrict__ node_idx, const float* __restrict__ a2hi)
{
    int w = (blockIdx.x * blockDim.x + threadIdx.x) >> 5;
    if (w >= N_EDGES) return;
    int lane = threadIdx.x & 31;
    const int q = lane >> 1, r = lane & 1;
    int s = g_eoff[w], epos = g_eoff[w + 1];

    float4 acc = make_float4(0.f, 0.f, 0.f, 0.f);
    float usum = 0.f;
    for (int t0 = s; t0 < epos; t0 += 32) {
#pragma unroll
        for (int k = 0; k < 2; k++) {
            int i = t0 + k * 16 + q;
            if (i < epos) {
                int nd = __ldg(node_idx + i);
                const float* row = g_hu2 + (size_t)nd * 12;
                float4 v = *(const float4*)(row + r * 4);
                acc.x += v.x; acc.y += v.y; acc.z += v.z; acc.w += v.w;
                if (r == 1) usum += __ldg(row + 8);
            }
        }
    }
#pragma unroll
    for (int o = 16; o >= 2; o >>= 1) {
        acc.x += __shfl_down_sync(0xffffffffu, acc.x, o);
        acc.y += __shfl_down_sync(0xffffffffu, acc.y, o);
        acc.z += __shfl_down_sync(0xffffffffu, acc.z, o);
        acc.w += __shfl_down_sync(0xffffffffu, acc.w, o);
    }
#pragma unroll
    for (int o = 16; o; o >>= 1) usum += __shfl_xor_sync(0xffffffffu, usum, o);
    float inv = 1.f / (usum + 1e-9f);

    float t2p = 0.f;
    if (lane < 2) {
        float4 val = make_float4(acc.x * inv, acc.y * inv, acc.z * inv, acc.w * inv);
        *(float4*)(g_et2 + (size_t)w * 12 + r * 4) = val;
        t2p = val.x * __ldg(a2hi + r * 4) + val.y * __ldg(a2hi + r * 4 + 1)
            + val.z * __ldg(a2hi + r * 4 + 2);
        if (r == 0) t2p += val.w * __ldg(a2hi + 3);   // a2hi[7] does not exist
    }
    t2p += __shfl_xor_sync(0xffffffffu, t2p, 1);
    if (lane == 0) g_et2[(size_t)w * 12 + 8] = t2p;
}

// ---------------- phase 2, layer 2 + fused log_softmax ---------------------
__global__ void k_phase2_l2(float* __restrict__ H2out, float* __restrict__ logp)
{
    int n = (blockIdx.x * blockDim.x + threadIdx.x) >> 5;
    if (n >= N_NODES) return;
    int lane = threadIdx.x & 31;
    const int q = lane >> 1, r = lane & 1;
    int s = g_noff[n], e = g_noff[n + 1];
    float t1n = g_t1[n];

    float4 acc = make_float4(0.f, 0.f, 0.f, 0.f);
    float wsum = 0.f;
    for (int t0 = s; t0 < e; t0 += 32) {
#pragma unroll
        for (int k = 0; k < 2; k++) {
            int i = t0 + k * 16 + q;
            bool act = (i < e);
            int ed = act ? __ldg(g_pedge + i) : 0;
            const float* row = g_et2 + (size_t)ed * 12;
            float4 v = make_float4(0.f, 0.f, 0.f, 0.f);
            if (act) v = *(const float4*)(row + r * 4);
            float wv = 0.f;
            if (r == 1 && act) wv = __expf(lrelu(t1n + __ldg(row + 8)));
            float wvb = __shfl_sync(0xffffffffu, wv, lane | 1);
            if (r == 1) wsum += wv;
            acc.x += wvb * v.x; acc.y += wvb * v.y;
            acc.z += wvb * v.z; acc.w += wvb * v.w;
        }
    }
#pragma unroll
    for (int o = 16; o >= 2; o >>= 1) {
        acc.x += __shfl_down_sync(0xffffffffu, acc.x, o);
        acc.y += __shfl_down_sync(0xffffffffu, acc.y, o);
        acc.z += __shfl_down_sync(0xffffffffu, acc.z, o);
        acc.w += __shfl_down_sync(0xffffffffu, acc.w, o);
    }
#pragma unroll
    for (int o = 16; o; o >>= 1) wsum += __shfl_xor_sync(0xffffffffu, wsum, o);
    float inv = 1.f / (wsum + 1e-9f);
    float4 h24 = make_float4(acc.x * inv, acc.y * inv, acc.z * inv, acc.w * inv);

    // redistribute to lanes 0..7 (lane j takes component j&3 from lane j>>2)
    float cx = __shfl_sync(0xffffffffu, h24.x, lane >> 2);
    float cy = __shfl_sync(0xffffffffu, h24.y, lane >> 2);
    float cz = __shfl_sync(0xffffffffu, h24.z, lane >> 2);
    float cw = __shfl_sync(0xffffffffu, h24.w, lane >> 2);
    int sel = lane & 3;
    float val = (sel == 0) ? cx : (sel == 1) ? cy : (sel == 2) ? cz : cw;

    float v = (lane < N_CLS) ? val : -1e30f;
    if (lane < N_CLS) H2out[(size_t)n * N_CLS + lane] = v;

    // log_softmax over the 8-lane group
    float m = v;
    m = fmaxf(m, __shfl_xor_sync(0xffffffffu, m, 4));
    m = fmaxf(m, __shfl_xor_sync(0xffffffffu, m, 2));
    m = fmaxf(m, __shfl_xor_sync(0xffffffffu, m, 1));
    float ex = (lane < N_CLS) ? __expf(v - m) : 0.f;
    ex += __shfl_xor_sync(0xffffffffu, ex, 4);
    ex += __shfl_xor_sync(0xffffffffu, ex, 2);
    ex += __shfl_xor_sync(0xffffffffu, ex, 1);
    float ls = m + __logf(ex);
    if (lane < N_CLS) logp[(size_t)n * N_CLS + lane] = v - ls;
}

// ---------------- launch ---------------------------------------------------
extern "C" void kernel_launch(void* const* d_in, const int* in_sizes, int n_in,
                              void* d_out, int out_size)
{
    const float* H   = (const float*)d_in[0];
    const float* W1  = (const float*)d_in[1];
    const float* a11 = (const float*)d_in[2];
    const float* a21 = (const float*)d_in[3];
    const float* W2  = (const float*)d_in[4];
    const float* a12 = (const float*)d_in[5];
    const float* a22 = (const float*)d_in[6];
    const int* node_idx = (const int*)d_in[7];
    const int* edge_idx = (const int*)d_in[8];

    float* out  = (float*)d_out;
    float* logp = out;                                              // [N, 7]
    float* H1   = out + (size_t)N_NODES * N_CLS;                    // [N, 16]
    float* H2   = out + (size_t)N_NODES * (N_CLS + D_HID);          // [N, 7]

    static cudaStream_t s1 = nullptr;
    static cudaEvent_t evF = nullptr, evJ = nullptr;
    static void* cnt_ptr = nullptr;
    if (s1 == nullptr) {
        cudaStreamCreateWithFlags(&s1, cudaStreamNonBlocking);
        cudaEventCreateWithFlags(&evF, cudaEventDisableTiming);
        cudaEventCreateWithFlags(&evJ, cudaEventDisableTiming);
        cudaGetSymbolAddress(&cnt_ptr, g_cnt);
    }

    // fork
    cudaEventRecord(evF, 0);
    cudaStreamWaitEvent(s1, evF, 0);

    k_eoff<<<(N_EDGES + 255) / 256, 256>>>(edge_idx);

    cudaMemsetAsync(cnt_ptr, 0, N_NODES * sizeof(int), s1);
    k_count<<<(NNZ / 4 + 255) / 256, 256, 0, s1>>>((const int4*)node_idx);
    k_scan1<<<100, 1024, 0, s1>>>();
    k_scan2<<<1, 128, 0, s1>>>();
    k_scan3<<<100, 1024, 0, s1>>>();

    k_gemm1<<<(N_NODES + 127) / 128, 128>>>(H, W1, a11, a21);

    k_scatter<<<(NNZ / 4 + 255) / 256, 256, 0, s1>>>((const int4*)node_idx,
                                                     (const int4*)edge_idx);
    cudaEventRecord(evJ, s1);

    k_phase1_l1<<<N_EDGES / 8, 256>>>(node_idx, a21 + D_HID);

    cudaStreamWaitEvent(0, evJ, 0);

    k_phase2_l1<<<N_NODES / 8, 256>>>(H1, W2, a12, a22);
    k_phase1_l2<<<N_EDGES / 8, 256>>>(node_idx, a22 + N_CLS);
    k_phase2_l2<<<N_NODES / 8, 256>>>(H2, logp);
}

// round 6
// speedup vs baseline: 1.5994x; 1.0294x over previous
#include <cuda_runtime.h>
#include <cuda_fp16.h>
#include <cstdint>
#include <cstddef>

#define N_NODES 100000
#define N_EDGES 100000
#define NNZ     3200000
#define D_IN    512
#define D_HID   16
#define N_CLS   7
#define LOG2E   1.4426950408889634f

// ---------------- scratch (device globals) ---------------------------------
__device__ __half g_hu1h[(size_t)N_NODES * 16];  // layer1 node rows: h*u fp16 (32B)
__device__ float  g_u1[N_NODES];                 // u = exp(lrelu(h.a1)) fp32
__device__ __half g_e1h[(size_t)N_EDGES * 16];   // layer1 edge rows: e fp16 (32B)
__device__ float  g_t2e1[N_EDGES];               // (e.a2hi)*log2e fp32
__device__ __half g_hu2h[(size_t)N_NODES * 8];   // layer2 node rows: h2*u fp16, pad (16B)
__device__ float  g_u2[N_NODES];
__device__ __half g_e2h[(size_t)N_EDGES * 8];    // layer2 edge rows: e2 fp16, pad (16B)
__device__ float  g_t2e2[N_EDGES];
__device__ float  g_t1[N_NODES];                 // (h.a2lo)*log2e
__device__ int    g_eoff[N_EDGES + 1];
__device__ int    g_cnt[N_NODES];
__device__ int    g_noff[N_NODES + 1];
__device__ int    g_cur[N_NODES];
__device__ int    g_pedge[NNZ];
__device__ int    g_bsum[128];
__device__ int    g_bpre[128];

__device__ __forceinline__ float lrelu(float v) { return v > 0.f ? v : 0.2f * v; }

// ---- packed f32x2 helpers --------------------------------------------------
__device__ __forceinline__ unsigned long long splat2(float x) {
    unsigned long long r;
    unsigned int u = __float_as_uint(x);
    asm("mov.b64 %0, {%1, %1};" : "=l"(r) : "r"(u));
    return r;
}
__device__ __forceinline__ unsigned long long ffma2(unsigned long long a,
                                                    unsigned long long b,
                                                    unsigned long long c) {
    unsigned long long d;
    asm("fma.rn.f32x2 %0, %1, %2, %3;" : "=l"(d) : "l"(a), "l"(b), "l"(c));
    return d;
}
__device__ __forceinline__ void unpack2(unsigned long long v, float& lo, float& hi) {
    unsigned int a, b;
    asm("mov.b64 {%0, %1}, %2;" : "=r"(a), "=r"(b) : "l"(v));
    lo = __uint_as_float(a);
    hi = __uint_as_float(b);
}
// accumulate 8 halves (uint4) into 8 fp32 accs
__device__ __forceinline__ void acc8(const uint4& v, float* acc, float w) {
    __half2 h0 = *(const __half2*)&v.x;
    __half2 h1 = *(const __half2*)&v.y;
    __half2 h2 = *(const __half2*)&v.z;
    __half2 h3 = *(const __half2*)&v.w;
    float2 f0 = __half22float2(h0), f1 = __half22float2(h1);
    float2 f2 = __half22float2(h2), f3 = __half22float2(h3);
    acc[0] += w * f0.x; acc[1] += w * f0.y;
    acc[2] += w * f1.x; acc[3] += w * f1.y;
    acc[4] += w * f2.x; acc[5] += w * f2.y;
    acc[6] += w * f3.x; acc[7] += w * f3.y;
}
__device__ __forceinline__ void add8(const uint4& v, float* acc) {
    __half2 h0 = *(const __half2*)&v.x;
    __half2 h1 = *(const __half2*)&v.y;
    __half2 h2 = *(const __half2*)&v.z;
    __half2 h3 = *(const __half2*)&v.w;
    float2 f0 = __half22float2(h0), f1 = __half22float2(h1);
    float2 f2 = __half22float2(h2), f3 = __half22float2(h3);
    acc[0] += f0.x; acc[1] += f0.y;
    acc[2] += f1.x; acc[3] += f1.y;
    acc[4] += f2.x; acc[5] += f2.y;
    acc[6] += f3.x; acc[7] += f3.y;
}
__device__ __forceinline__ uint4 pack8(const float* e) {
    __half2 p[4];
    p[0] = __float22half2_rn(make_float2(e[0], e[1]));
    p[1] = __float22half2_rn(make_float2(e[2], e[3]));
    p[2] = __float22half2_rn(make_float2(e[4], e[5]));
    p[3] = __float22half2_rn(make_float2(e[6], e[7]));
    return *(uint4*)p;
}

// ---------------- GEMM1: h = X @ W1 (FFMA2); epilogue writes fp16 rows -----
__global__ void k_gemm1(const float* __restrict__ X, const float* __restrict__ W,
                        const float* __restrict__ a1, const float* __restrict__ a2lo)
{
    __shared__ __align__(16) float sX[128 * 65];
    __shared__ __align__(16) float sW[64 * 16];
    const int t = threadIdx.x;
    const int nbase = blockIdx.x * 128;
    const int ng = t >> 2, jg = t & 3;

    unsigned long long acc[4][2];
#pragma unroll
    for (int a = 0; a < 4; a++) { acc[a][0] = 0ull; acc[a][1] = 0ull; }

    for (int ck = 0; ck < D_IN; ck += 64) {
        for (int q = t; q < 128 * 16; q += 128) {
            int row = q >> 4, fc = q & 15;
            int n = nbase + row;
            float4 v = make_float4(0.f, 0.f, 0.f, 0.f);
            if (n < N_NODES) v = *(const float4*)(X + (size_t)n * D_IN + ck + fc * 4);
            int b = row * 65 + fc * 4;
            sX[b] = v.x; sX[b + 1] = v.y; sX[b + 2] = v.z; sX[b + 3] = v.w;
        }
        for (int q = t; q < 256; q += 128) {
            float4 v = *(const float4*)(W + ck * 16 + q * 4);
            *(float4*)(sW + q * 4) = v;
        }
        __syncthreads();
#pragma unroll 16
        for (int c = 0; c < 64; c++) {
            unsigned long long wp0 = *(const unsigned long long*)(sW + c * 16 + jg * 4);
            unsigned long long wp1 = *(const unsigned long long*)(sW + c * 16 + jg * 4 + 2);
#pragma unroll
            for (int a = 0; a < 4; a++) {
                unsigned long long xs = splat2(sX[(ng * 4 + a) * 65 + c]);
                acc[a][0] = ffma2(xs, wp0, acc[a][0]);
                acc[a][1] = ffma2(xs, wp1, acc[a][1]);
            }
        }
        __syncthreads();
    }

#pragma unroll
    for (int a = 0; a < 4; a++) {
        float v0, v1, v2, v3;
        unpack2(acc[a][0], v0, v1);
        unpack2(acc[a][1], v2, v3);
        int j = jg * 4;
        int srow = (ng * 4 + a) * 17;
        sX[srow + j] = v0; sX[srow + j + 1] = v1;
        sX[srow + j + 2] = v2; sX[srow + j + 3] = v3;
    }
    __syncthreads();
    {
        int n = nbase + t;
        if (n < N_NODES) {
            float hv[16];
            float uu = 0.f, tt = 0.f;
#pragma unroll
            for (int j = 0; j < D_HID; j++) {
                hv[j] = sX[t * 17 + j];
                uu += hv[j] * __ldg(a1 + j);
                tt += hv[j] * __ldg(a2lo + j);
            }
            float u = exp2f(lrelu(uu * LOG2E));
            float e0[8], e1[8];
#pragma unroll
            for (int j = 0; j < 8; j++) { e0[j] = hv[j] * u; e1[j] = hv[8 + j] * u; }
            __half* dst = g_hu1h + (size_t)n * 16;
            *(uint4*)dst = pack8(e0);
            *(uint4*)(dst + 8) = pack8(e1);
            g_u1[n] = u;
            g_t1[n] = tt * LOG2E;
        }
    }
}

// ---------------- edge offsets: lower_bound over sorted edge_idx -----------
__global__ void k_eoff(const int* __restrict__ edge_idx)
{
    int e = blockIdx.x * blockDim.x + threadIdx.x;
    if (e >= N_EDGES) return;
    int lo = 0, hi = NNZ;
    while (lo < hi) {
        int m = (lo + hi) >> 1;
        if (__ldg(edge_idx + m) < e) lo = m + 1; else hi = m;
    }
    g_eoff[e] = lo;
    if (e == 0) g_eoff[N_EDGES] = NNZ;
}

// ---------------- node CSR build -------------------------------------------
__global__ void k_count(const int4* __restrict__ node_idx4)
{
    int i = blockIdx.x * blockDim.x + threadIdx.x;
    if (i >= NNZ / 4) return;
    int4 v = node_idx4[i];
    atomicAdd(&g_cnt[v.x], 1);
    atomicAdd(&g_cnt[v.y], 1);
    atomicAdd(&g_cnt[v.z], 1);
    atomicAdd(&g_cnt[v.w], 1);
}
__global__ void k_scan1()
{
    __shared__ int sp[1024];
    int t = threadIdx.x, b = blockIdx.x;
    int idx = b * 1000 + t;
    int v = (t < 1000) ? g_cnt[idx] : 0;
    sp[t] = v;
    __syncthreads();
    for (int o = 1; o < 1024; o <<= 1) {
        int u = (t >= o) ? sp[t - o] : 0;
        __syncthreads();
        sp[t] += u;
        __syncthreads();
    }
    if (t < 1000) g_noff[idx] = sp[t] - v;
    if (t == 1023) g_bsum[b] = sp[1023];
}
__global__ void k_scan2()
{
    __shared__ int sp[128];
    int t = threadIdx.x;
    int v = (t < 100) ? g_bsum[t] : 0;
    sp[t] = v;
    __syncthreads();
    for (int o = 1; o < 128; o <<= 1) {
        int u = (t >= o) ? sp[t - o] : 0;
        __syncthreads();
        sp[t] += u;
        __syncthreads();
    }
    if (t < 100) g_bpre[t] = sp[t] - v;
}
__global__ void k_scan3()
{
    int t = threadIdx.x, b = blockIdx.x;
    int idx = b * 1000 + t;
    if (t < 1000) {
        int o = g_noff[idx] + g_bpre[b];
        g_noff[idx] = o;
        g_cur[idx] = o;
    }
    if (idx == 0) g_noff[N_NODES] = NNZ;
}
__global__ void k_scatter(const int4* __restrict__ node_idx4, const int4* __restrict__ edge_idx4)
{
    int i = blockIdx.x * blockDim.x + threadIdx.x;
    if (i >= NNZ / 4) return;
    int4 nd = node_idx4[i];
    int4 ed = edge_idx4[i];
    g_pedge[atomicAdd(&g_cur[nd.x], 1)] = ed.x;
    g_pedge[atomicAdd(&g_cur[nd.y], 1)] = ed.y;
    g_pedge[atomicAdd(&g_cur[nd.z], 1)] = ed.z;
    g_pedge[atomicAdd(&g_cur[nd.w], 1)] = ed.w;
}

// ---------------- phase 1, layer 1: warp/edge, 2 lanes per fp16 row --------
__global__ void k_phase1_l1(const int* __restrict__ node_idx, const float* __restrict__ a2hi)
{
    int w = (blockIdx.x * blockDim.x + threadIdx.x) >> 5;
    if (w >= N_EDGES) return;
    int lane = threadIdx.x & 31;
    const int q = lane >> 1, r = lane & 1;
    int s = g_eoff[w], epos = g_eoff[w + 1];

    float acc[8];
#pragma unroll
    for (int k = 0; k < 8; k++) acc[k] = 0.f;
    float usum = 0.f;

    for (int t0 = s; t0 < epos; t0 += 32) {
#pragma unroll
        for (int kk = 0; kk < 2; kk++) {
            int i = t0 + kk * 16 + q;
            if (i < epos) {
                int nd = __ldg(node_idx + i);
                uint4 v = *((const uint4*)(g_hu1h + (size_t)nd * 16) + r);
                add8(v, acc);
                if (r == 0) usum += __ldg(g_u1 + nd);
            }
        }
    }
    // reduce over the 16 groups; lane0 = feats 0-7, lane1 = feats 8-15
#pragma unroll
    for (int o = 16; o >= 2; o >>= 1)
#pragma unroll
        for (int k = 0; k < 8; k++)
            acc[k] += __shfl_down_sync(0xffffffffu, acc[k], o);
#pragma unroll
    for (int o = 16; o; o >>= 1) usum += __shfl_xor_sync(0xffffffffu, usum, o);
    float inv = 1.f / (usum + 1e-9f);

    float t2p = 0.f;
    if (lane < 2) {
        float e8[8];
#pragma unroll
        for (int k = 0; k < 8; k++) {
            e8[k] = acc[k] * inv;
            t2p += e8[k] * __ldg(a2hi + lane * 8 + k);
        }
        *((uint4*)(g_e1h + (size_t)w * 16) + lane) = pack8(e8);
    }
    t2p += __shfl_xor_sync(0xffffffffu, t2p, 1);
    if (lane == 0) g_t2e1[w] = t2p * LOG2E;
}

// ---------------- phase 2, layer 1 + fused gemm2 epilogue ------------------
__global__ void k_phase2_l1(float* __restrict__ H1out, const float* __restrict__ W2,
                            const float* __restrict__ a1, const float* __restrict__ a2lo)
{
    int n = (blockIdx.x * blockDim.x + threadIdx.x) >> 5;
    if (n >= N_NODES) return;
    int lane = threadIdx.x & 31;
    const int q = lane >> 1, r = lane & 1;
    int s = g_noff[n], e = g_noff[n + 1];
    float t1n = g_t1[n];

    float acc[8];
#pragma unroll
    for (int k = 0; k < 8; k++) acc[k] = 0.f;
    float wsum = 0.f;

    for (int t0 = s; t0 < e; t0 += 32) {
#pragma unroll
        for (int kk = 0; kk < 2; kk++) {
            int i = t0 + kk * 16 + q;
            bool act = (i < e);
            int ed = act ? __ldg(g_pedge + i) : 0;
            float wv = 0.f;
            if (r == 1 && act) wv = exp2f(lrelu(t1n + __ldg(g_t2e1 + ed)));
            float wvb = __shfl_sync(0xffffffffu, wv, lane | 1);
            if (r == 1) wsum += wv;
            uint4 v = make_uint4(0u, 0u, 0u, 0u);
            if (act) v = *((const uint4*)(g_e1h + (size_t)ed * 16) + r);
            acc8(v, acc, wvb);
        }
    }
#pragma unroll
    for (int o = 16; o >= 2; o >>= 1)
#pragma unroll
        for (int k = 0; k < 8; k++)
            acc[k] += __shfl_down_sync(0xffffffffu, acc[k], o);
#pragma unroll
    for (int o = 16; o; o >>= 1) wsum += __shfl_xor_sync(0xffffffffu, wsum, o);
    float inv = 1.f / (wsum + 1e-9f);

    float hk[8];
#pragma unroll
    for (int k = 0; k < 8; k++) hk[k] = acc[k] * inv;
    if (lane < 2) {
        *(float4*)(H1out + (size_t)n * 16 + lane * 8) =
            make_float4(hk[0], hk[1], hk[2], hk[3]);
        *(float4*)(H1out + (size_t)n * 16 + lane * 8 + 4) =
            make_float4(hk[4], hk[5], hk[6], hk[7]);
    }

    // redistribute H1 to lanes 0..15: lane j gets hk[j&7] from lane j>>3
    float h1 = 0.f;
#pragma unroll
    for (int k = 0; k < 8; k++) {
        float tv = __shfl_sync(0xffffffffu, hk[k], lane >> 3);
        if ((lane & 7) == k) h1 = tv;
    }

    // fused gemm2: h2 = elu(h1) @ W2, plus u/t1 for layer 2
    float x = 0.f;
    float w2r[N_CLS];
    if (lane < 16) {
        x = h1 > 0.f ? h1 : expm1f(h1);
#pragma unroll
        for (int jj = 0; jj < N_CLS; jj++) w2r[jj] = __ldg(W2 + lane * N_CLS + jj);
    } else {
#pragma unroll
        for (int jj = 0; jj < N_CLS; jj++) w2r[jj] = 0.f;
    }
    float sarr[N_CLS];
#pragma unroll
    for (int jj = 0; jj < N_CLS; jj++) {
        float p = x * w2r[jj];
        p += __shfl_xor_sync(0xffffffffu, p, 8);
        p += __shfl_xor_sync(0xffffffffu, p, 4);
        p += __shfl_xor_sync(0xffffffffu, p, 2);
        p += __shfl_xor_sync(0xffffffffu, p, 1);
        sarr[jj] = p;   // valid in lanes 0..15
    }
    if (lane == 0) {
        float uu = 0.f, tt = 0.f;
#pragma unroll
        for (int jj = 0; jj < N_CLS; jj++) {
            uu += sarr[jj] * __ldg(a1 + jj);
            tt += sarr[jj] * __ldg(a2lo + jj);
        }
        float u = exp2f(lrelu(uu * LOG2E));
        float e8[8];
#pragma unroll
        for (int jj = 0; jj < N_CLS; jj++) e8[jj] = sarr[jj] * u;
        e8[7] = 0.f;
        *(uint4*)(g_hu2h + (size_t)n * 8) = pack8(e8);
        g_u2[n] = u;
        g_t1[n] = tt * LOG2E;
    }
}

// ---------------- phase 1, layer 2: warp/edge, 1 lane per fp16 row ---------
__global__ void k_phase1_l2(const int* __restrict__ node_idx, const float* __restrict__ a2hi)
{
    int w = (blockIdx.x * blockDim.x + threadIdx.x) >> 5;
    if (w >= N_EDGES) return;
    int lane = threadIdx.x & 31;
    int s = g_eoff[w], epos = g_eoff[w + 1];

    float acc[8];
#pragma unroll
    for (int k = 0; k < 8; k++) acc[k] = 0.f;
    float usum = 0.f;

    for (int t0 = s; t0 < epos; t0 += 32) {
        int i = t0 + lane;
        if (i < epos) {
            int nd = __ldg(node_idx + i);
            uint4 v = *(const uint4*)(g_hu2h + (size_t)nd * 8);
            add8(v, acc);
            usum += __ldg(g_u2 + nd);
        }
    }
#pragma unroll
    for (int o = 16; o >= 1; o >>= 1)
#pragma unroll
        for (int k = 0; k < 8; k++)
            acc[k] += __shfl_down_sync(0xffffffffu, acc[k], o);
#pragma unroll
    for (int o = 16; o; o >>= 1) usum += __shfl_xor_sync(0xffffffffu, usum, o);

    if (lane == 0) {
        float inv = 1.f / (usum + 1e-9f);
        float e8[8];
        float t2 = 0.f;
#pragma unroll
        for (int k = 0; k < 7; k++) {
            e8[k] = acc[k] * inv;
            t2 += e8[k] * __ldg(a2hi + k);
        }
        e8[7] = 0.f;
        *(uint4*)(g_e2h + (size_t)w * 8) = pack8(e8);
        g_t2e2[w] = t2 * LOG2E;
    }
}

// ---------------- phase 2, layer 2 + fused log_softmax ---------------------
__global__ void k_phase2_l2(float* __restrict__ H2out, float* __restrict__ logp)
{
    int n = (blockIdx.x * blockDim.x + threadIdx.x) >> 5;
    if (n >= N_NODES) return;
    int lane = threadIdx.x & 31;
    int s = g_noff[n], e = g_noff[n + 1];
    float t1n = g_t1[n];

    float acc[8];
#pragma unroll
    for (int k = 0; k < 8; k++) acc[k] = 0.f;
    float wsum = 0.f;

    for (int t0 = s; t0 < e; t0 += 32) {
        int i = t0 + lane;
        if (i < e) {
            int ed = __ldg(g_pedge + i);
            float wv = exp2f(lrelu(t1n + __ldg(g_t2e2 + ed)));
            wsum += wv;
            uint4 v = *(const uint4*)(g_e2h + (size_t)ed * 8);
            acc8(v, acc, wv);
        }
    }
#pragma unroll
    for (int o = 16; o >= 1; o >>= 1)
#pragma unroll
        for (int k = 0; k < 8; k++)
            acc[k] += __shfl_down_sync(0xffffffffu, acc[k], o);
#pragma unroll
    for (int o = 16; o; o >>= 1) wsum += __shfl_xor_sync(0xffffffffu, wsum, o);

    if (lane == 0) {
        float inv = 1.f / (wsum + 1e-9f);
        float v[N_CLS];
        float m = -1e30f;
#pragma unroll
        for (int k = 0; k < N_CLS; k++) {
            v[k] = acc[k] * inv;
            m = fmaxf(m, v[k]);
        }
        float sx = 0.f;
#pragma unroll
        for (int k = 0; k < N_CLS; k++) sx += __expf(v[k] - m);
        float ls = m + __logf(sx);
        float* h2p = H2out + (size_t)n * N_CLS;
        float* lpp = logp + (size_t)n * N_CLS;
#pragma unroll
        for (int k = 0; k < N_CLS; k++) {
            h2p[k] = v[k];
            lpp[k] = v[k] - ls;
        }
    }
}

// ---------------- launch ---------------------------------------------------
extern "C" void kernel_launch(void* const* d_in, const int* in_sizes, int n_in,
                              void* d_out, int out_size)
{
    const float* H   = (const float*)d_in[0];
    const float* W1  = (const float*)d_in[1];
    const float* a11 = (const float*)d_in[2];
    const float* a21 = (const float*)d_in[3];
    const float* W2  = (const float*)d_in[4];
    const float* a12 = (const float*)d_in[5];
    const float* a22 = (const float*)d_in[6];
    const int* node_idx = (const int*)d_in[7];
    const int* edge_idx = (const int*)d_in[8];

    float* out  = (float*)d_out;
    float* logp = out;                                              // [N, 7]
    float* H1   = out + (size_t)N_NODES * N_CLS;                    // [N, 16]
    float* H2   = out + (size_t)N_NODES * (N_CLS + D_HID);          // [N, 7]

    static cudaStream_t s1 = nullptr;
    static cudaEvent_t evF = nullptr, evJ = nullptr;
    static void* cnt_ptr = nullptr;
    if (s1 == nullptr) {
        cudaStreamCreateWithFlags(&s1, cudaStreamNonBlocking);
        cudaEventCreateWithFlags(&evF, cudaEventDisableTiming);
        cudaEventCreateWithFlags(&evJ, cudaEventDisableTiming);
        cudaGetSymbolAddress(&cnt_ptr, g_cnt);
    }

    // fork
    cudaEventRecord(evF, 0);
    cudaStreamWaitEvent(s1, evF, 0);

    k_eoff<<<(N_EDGES + 255) / 256, 256>>>(edge_idx);

    cudaMemsetAsync(cnt_ptr, 0, N_NODES * sizeof(int), s1);
    k_count<<<(NNZ / 4 + 255) / 256, 256, 0, s1>>>((const int4*)node_idx);
    k_scan1<<<100, 1024, 0, s1>>>();
    k_scan2<<<1, 128, 0, s1>>>();
    k_scan3<<<100, 1024, 0, s1>>>();

    k_gemm1<<<(N_NODES + 127) / 128, 128>>>(H, W1, a11, a21);

    k_scatter<<<(NNZ / 4 + 255) / 256, 256, 0, s1>>>((const int4*)node_idx,
                                                     (const int4*)edge_idx);
    cudaEventRecord(evJ, s1);

    k_phase1_l1<<<N_EDGES / 8, 256>>>(node_idx, a21 + D_HID);

    cudaStreamWaitEvent(0, evJ, 0);

    k_phase2_l1<<<N_NODES / 8, 256>>>(H1, W2, a12, a22);
    k_phase1_l2<<<N_EDGES / 8, 256>>>(node_idx, a22 + N_CLS);
    k_phase2_l2<<<N_NODES / 8, 256>>>(H2, logp);
}

// round 8
// speedup vs baseline: 2.1340x; 1.3342x over previous
#include <cuda_runtime.h>
#include <cuda_fp16.h>
#include <cstdint>
#include <cstddef>

#define N_NODES 100000
#define N_EDGES 100000
#define NNZ     3200000
#define D_IN    512
#define D_HID   16
#define N_CLS   7
#define LOG2E   1.4426950408889634f
#define FULLM   0xffffffffu

// ---------------- scratch (device globals) ---------------------------------
__device__ __align__(16) __half g_hu1h[(size_t)N_NODES * 16]; // L1 node rows: h*u fp16 (32B)
__device__ float  g_u1[N_NODES];                              // u fp32
__device__ __align__(16) __half g_e1h[(size_t)N_EDGES * 16];  // L1 edge rows: e fp16 (32B)
__device__ float  g_t2e1[N_EDGES];                            // (e.a2hi)*log2e fp32
__device__ __align__(16) __half g_hu2h[(size_t)N_NODES * 8];  // L2 node rows: [h2*u (7), u] (16B)
__device__ __align__(16) __half g_e2h[(size_t)N_EDGES * 8];   // L2 edge rows: [e2 (7), t2*log2e] (16B)
__device__ float  g_t1[N_NODES];                              // (h.a2lo)*log2e
__device__ int    g_eoff[N_EDGES + 1];
__device__ int    g_cnt[N_NODES];
__device__ int    g_noff[N_NODES + 1];
__device__ int    g_cur[N_NODES];
__device__ int    g_pedge[NNZ];
__device__ int    g_bsum[128];
__device__ int    g_bpre[128];

__device__ __forceinline__ float lrelu(float v) { return v > 0.f ? v : 0.2f * v; }

// ---- packed f32x2 helpers --------------------------------------------------
__device__ __forceinline__ unsigned long long splat2(float x) {
    unsigned long long r;
    unsigned int u = __float_as_uint(x);
    asm("mov.b64 %0, {%1, %1};" : "=l"(r) : "r"(u));
    return r;
}
__device__ __forceinline__ unsigned long long ffma2(unsigned long long a,
                                                    unsigned long long b,
                                                    unsigned long long c) {
    unsigned long long d;
    asm("fma.rn.f32x2 %0, %1, %2, %3;" : "=l"(d) : "l"(a), "l"(b), "l"(c));
    return d;
}
__device__ __forceinline__ void unpack2(unsigned long long v, float& lo, float& hi) {
    unsigned int a, b;
    asm("mov.b64 {%0, %1}, %2;" : "=r"(a), "=r"(b) : "l"(v));
    lo = __uint_as_float(a);
    hi = __uint_as_float(b);
}
// accumulate 8 halves (uint4) into 8 fp32 accs
__device__ __forceinline__ void acc8(const uint4& v, float* acc, float w) {
    float2 f0 = __half22float2(*(const __half2*)&v.x);
    float2 f1 = __half22float2(*(const __half2*)&v.y);
    float2 f2 = __half22float2(*(const __half2*)&v.z);
    float2 f3 = __half22float2(*(const __half2*)&v.w);
    acc[0] += w * f0.x; acc[1] += w * f0.y;
    acc[2] += w * f1.x; acc[3] += w * f1.y;
    acc[4] += w * f2.x; acc[5] += w * f2.y;
    acc[6] += w * f3.x; acc[7] += w * f3.y;
}
__device__ __forceinline__ void add8(const uint4& v, float* acc) {
    float2 f0 = __half22float2(*(const __half2*)&v.x);
    float2 f1 = __half22float2(*(const __half2*)&v.y);
    float2 f2 = __half22float2(*(const __half2*)&v.z);
    float2 f3 = __half22float2(*(const __half2*)&v.w);
    acc[0] += f0.x; acc[1] += f0.y;
    acc[2] += f1.x; acc[3] += f1.y;
    acc[4] += f2.x; acc[5] += f2.y;
    acc[6] += f3.x; acc[7] += f3.y;
}
__device__ __forceinline__ uint4 pack8(const float* e) {
    __half2 p[4];
    p[0] = __float22half2_rn(make_float2(e[0], e[1]));
    p[1] = __float22half2_rn(make_float2(e[2], e[3]));
    p[2] = __float22half2_rn(make_float2(e[4], e[5]));
    p[3] = __float22half2_rn(make_float2(e[6], e[7]));
    return *(uint4*)p;
}

// ---------------- GEMM1 -----------------------------------------------------
__global__ void k_gemm1(const float* __restrict__ X, const float* __restrict__ W,
                        const float* __restrict__ a1, const float* __restrict__ a2lo)
{
    __shared__ __align__(16) float sX[128 * 65];
    __shared__ __align__(16) float sW[64 * 16];
    const int t = threadIdx.x;
    const int nbase = blockIdx.x * 128;
    const int ng = t >> 2, jg = t & 3;

    unsigned long long acc[4][2];
#pragma unroll
    for (int a = 0; a < 4; a++) { acc[a][0] = 0ull; acc[a][1] = 0ull; }

    for (int ck = 0; ck < D_IN; ck += 64) {
        for (int q = t; q < 128 * 16; q += 128) {
            int row = q >> 4, fc = q & 15;
            int n = nbase + row;
            float4 v = make_float4(0.f, 0.f, 0.f, 0.f);
            if (n < N_NODES) v = *(const float4*)(X + (size_t)n * D_IN + ck + fc * 4);
            int b = row * 65 + fc * 4;
            sX[b] = v.x; sX[b + 1] = v.y; sX[b + 2] = v.z; sX[b + 3] = v.w;
        }
        for (int q = t; q < 256; q += 128) {
            float4 v = *(const float4*)(W + ck * 16 + q * 4);
            *(float4*)(sW + q * 4) = v;
        }
        __syncthreads();
#pragma unroll 16
        for (int c = 0; c < 64; c++) {
            unsigned long long wp0 = *(const unsigned long long*)(sW + c * 16 + jg * 4);
            unsigned long long wp1 = *(const unsigned long long*)(sW + c * 16 + jg * 4 + 2);
#pragma unroll
            for (int a = 0; a < 4; a++) {
                unsigned long long xs = splat2(sX[(ng * 4 + a) * 65 + c]);
                acc[a][0] = ffma2(xs, wp0, acc[a][0]);
                acc[a][1] = ffma2(xs, wp1, acc[a][1]);
            }
        }
        __syncthreads();
    }

#pragma unroll
    for (int a = 0; a < 4; a++) {
        float v0, v1, v2, v3;
        unpack2(acc[a][0], v0, v1);
        unpack2(acc[a][1], v2, v3);
        int j = jg * 4;
        int srow = (ng * 4 + a) * 17;
        sX[srow + j] = v0; sX[srow + j + 1] = v1;
        sX[srow + j + 2] = v2; sX[srow + j + 3] = v3;
    }
    __syncthreads();
    {
        int n = nbase + t;
        if (n < N_NODES) {
            float hv[16];
            float uu = 0.f, tt = 0.f;
#pragma unroll
            for (int j = 0; j < D_HID; j++) {
                hv[j] = sX[t * 17 + j];
                uu += hv[j] * __ldg(a1 + j);
                tt += hv[j] * __ldg(a2lo + j);
            }
            float u = exp2f(lrelu(uu * LOG2E));
            float e0[8], e1[8];
#pragma unroll
            for (int j = 0; j < 8; j++) { e0[j] = hv[j] * u; e1[j] = hv[8 + j] * u; }
            __half* dst = g_hu1h + (size_t)n * 16;
            *(uint4*)dst = pack8(e0);
            *(uint4*)(dst + 8) = pack8(e1);
            g_u1[n] = u;
            g_t1[n] = tt * LOG2E;
        }
    }
}

// ---------------- edge offsets ---------------------------------------------
__global__ void k_eoff(const int* __restrict__ edge_idx)
{
    int e = blockIdx.x * blockDim.x + threadIdx.x;
    if (e >= N_EDGES) return;
    int lo = 0, hi = NNZ;
    while (lo < hi) {
        int m = (lo + hi) >> 1;
        if (__ldg(edge_idx + m) < e) lo = m + 1; else hi = m;
    }
    g_eoff[e] = lo;
    if (e == 0) g_eoff[N_EDGES] = NNZ;
}

// ---------------- node CSR build -------------------------------------------
__global__ void k_count(const int4* __restrict__ node_idx4)
{
    int i = blockIdx.x * blockDim.x + threadIdx.x;
    if (i >= NNZ / 4) return;
    int4 v = node_idx4[i];
    atomicAdd(&g_cnt[v.x], 1);
    atomicAdd(&g_cnt[v.y], 1);
    atomicAdd(&g_cnt[v.z], 1);
    atomicAdd(&g_cnt[v.w], 1);
}
__global__ void k_scan1()
{
    __shared__ int sp[1024];
    int t = threadIdx.x, b = blockIdx.x;
    int idx = b * 1000 + t;
    int v = (t < 1000) ? g_cnt[idx] : 0;
    sp[t] = v;
    __syncthreads();
    for (int o = 1; o < 1024; o <<= 1) {
        int u = (t >= o) ? sp[t - o] : 0;
        __syncthreads();
        sp[t] += u;
        __syncthreads();
    }
    if (t < 1000) g_noff[idx] = sp[t] - v;
    if (t == 1023) g_bsum[b] = sp[1023];
}
__global__ void k_scan2()
{
    __shared__ int sp[128];
    int t = threadIdx.x;
    int v = (t < 100) ? g_bsum[t] : 0;
    sp[t] = v;
    __syncthreads();
    for (int o = 1; o < 128; o <<= 1) {
        int u = (t >= o) ? sp[t - o] : 0;
        __syncthreads();
        sp[t] += u;
        __syncthreads();
    }
    if (t < 100) g_bpre[t] = sp[t] - v;
}
__global__ void k_scan3()
{
    int t = threadIdx.x, b = blockIdx.x;
    int idx = b * 1000 + t;
    if (t < 1000) {
        int o = g_noff[idx] + g_bpre[b];
        g_noff[idx] = o;
        g_cur[idx] = o;
    }
    if (idx == 0) g_noff[N_NODES] = NNZ;
}
__global__ void k_scatter(const int4* __restrict__ node_idx4, const int4* __restrict__ edge_idx4)
{
    int i = blockIdx.x * blockDim.x + threadIdx.x;
    if (i >= NNZ / 4) return;
    int4 nd = node_idx4[i];
    int4 ed = edge_idx4[i];
    g_pedge[atomicAdd(&g_cur[nd.x], 1)] = ed.x;
    g_pedge[atomicAdd(&g_cur[nd.y], 1)] = ed.y;
    g_pedge[atomicAdd(&g_cur[nd.z], 1)] = ed.z;
    g_pedge[atomicAdd(&g_cur[nd.w], 1)] = ed.w;
}

// ---------------- phase 1, layer 1: 8-lane group per edge, 4 edges/warp ----
// No in-loop shuffles; post-loop shuffles only (all 32 lanes reconverge).
__global__ void k_phase1_l1(const int* __restrict__ node_idx, const float* __restrict__ a2hi)
{
    int gid = (blockIdx.x * blockDim.x + threadIdx.x) >> 3;
    if (gid >= N_EDGES) return;
    const int lane = threadIdx.x & 31;
    const int ll = lane & 7;           // lane within group
    const int r = ll & 1;              // which half of the row
    int s = __ldg(g_eoff + gid), epos = __ldg(g_eoff + gid + 1);

    float acc[8];
#pragma unroll
    for (int k = 0; k < 8; k++) acc[k] = 0.f;
    float usum = 0.f;

    for (int i = s + (ll >> 1); i < epos; i += 4) {
        int nd = __ldg(node_idx + i);
        uint4 v = *((const uint4*)(g_hu1h + (size_t)nd * 16) + r);
        add8(v, acc);
        if (r == 0) usum += __ldg(g_u1 + nd);
    }
    // reduce the 4 row-slots within the 8-lane group -> ll=0 (feats0-7), ll=1 (8-15)
#pragma unroll
    for (int o = 4; o >= 2; o >>= 1)
#pragma unroll
        for (int k = 0; k < 8; k++)
            acc[k] += __shfl_down_sync(FULLM, acc[k], o, 8);
    usum += __shfl_down_sync(FULLM, usum, 4, 8);
    usum += __shfl_down_sync(FULLM, usum, 2, 8);
    usum = __shfl_sync(FULLM, usum, 0, 8);           // broadcast group total
    float inv = 1.f / (usum + 1e-9f);

    float t2p = 0.f;
    if (ll < 2) {
        float e8[8];
#pragma unroll
        for (int k = 0; k < 8; k++) {
            e8[k] = acc[k] * inv;
            t2p += e8[k] * __ldg(a2hi + r * 8 + k);
        }
        *((uint4*)(g_e1h + (size_t)gid * 16) + r) = pack8(e8);
    }
    t2p += __shfl_xor_sync(FULLM, t2p, 1);
    if (ll == 0) g_t2e1[gid] = t2p * LOG2E;
}

// ---------------- phase 2, layer 1 + fused gemm2 epilogue ------------------
// Both lanes of a pair compute wv redundantly (same addresses -> L1 broadcast);
// NO shuffle inside the divergent loop.
__global__ void k_phase2_l1(float* __restrict__ H1out, const float* __restrict__ W2,
                            const float* __restrict__ a1, const float* __restrict__ a2lo)
{
    int gid = (blockIdx.x * blockDim.x + threadIdx.x) >> 3;
    if (gid >= N_NODES) return;
    const int lane = threadIdx.x & 31;
    const int ll = lane & 7;
    const int r = ll & 1;
    int s = __ldg(g_noff + gid), e = __ldg(g_noff + gid + 1);
    float t1n = __ldg(g_t1 + gid);

    float acc[8];
#pragma unroll
    for (int k = 0; k < 8; k++) acc[k] = 0.f;
    float wsum = 0.f;

    for (int i = s + (ll >> 1); i < e; i += 4) {
        int ed = __ldg(g_pedge + i);
        float wv = exp2f(lrelu(t1n + __ldg(g_t2e1 + ed)));
        if (r == 1) wsum += wv;                      // count each incidence once
        uint4 v = *((const uint4*)(g_e1h + (size_t)ed * 16) + r);
        acc8(v, acc, wv);
    }
#pragma unroll
    for (int o = 4; o >= 2; o >>= 1)
#pragma unroll
        for (int k = 0; k < 8; k++)
            acc[k] += __shfl_down_sync(FULLM, acc[k], o, 8);
    wsum += __shfl_down_sync(FULLM, wsum, 4, 8);
    wsum += __shfl_down_sync(FULLM, wsum, 2, 8);
    wsum = __shfl_sync(FULLM, wsum, 1, 8);           // totals live in lane 1 of group
    float inv = 1.f / (wsum + 1e-9f);

    // lanes ll=0,1 hold the two 8-feat halves of H1[gid]
    float hk[8];
#pragma unroll
    for (int k = 0; k < 8; k++) hk[k] = acc[k] * inv;
    if (ll < 2) {
        *(float4*)(H1out + (size_t)gid * 16 + r * 8) =
            make_float4(hk[0], hk[1], hk[2], hk[3]);
        *(float4*)(H1out + (size_t)gid * 16 + r * 8 + 4) =
            make_float4(hk[4], hk[5], hk[6], hk[7]);
    }

    // redistribute: lane ll gets h1[ll] (from lane 0) and h1[ll+8] (from lane 1)
    float h1a = 0.f, h1b = 0.f;
#pragma unroll
    for (int k = 0; k < 8; k++) {
        float t0 = __shfl_sync(FULLM, hk[k], 0, 8);
        float t1v = __shfl_sync(FULLM, hk[k], 1, 8);
        if (ll == k) { h1a = t0; h1b = t1v; }
    }
    // gemm2 over 8 lanes: lane ll covers input channels ll and ll+8
    float xa = h1a > 0.f ? h1a : expm1f(h1a);
    float xb = h1b > 0.f ? h1b : expm1f(h1b);
    float sarr[N_CLS];
#pragma unroll
    for (int jj = 0; jj < N_CLS; jj++) {
        float p = xa * __ldg(W2 + ll * N_CLS + jj) + xb * __ldg(W2 + (ll + 8) * N_CLS + jj);
        p += __shfl_down_sync(FULLM, p, 4, 8);
        p += __shfl_down_sync(FULLM, p, 2, 8);
        p += __shfl_down_sync(FULLM, p, 1, 8);
        sarr[jj] = p;   // valid in lane 0 of group
    }
    if (ll == 0) {
        float uu = 0.f, tt = 0.f;
#pragma unroll
        for (int jj = 0; jj < N_CLS; jj++) {
            uu += sarr[jj] * __ldg(a1 + jj);
            tt += sarr[jj] * __ldg(a2lo + jj);
        }
        float u = exp2f(lrelu(uu * LOG2E));
        float e8[8];
#pragma unroll
        for (int jj = 0; jj < N_CLS; jj++) e8[jj] = sarr[jj] * u;
        e8[7] = u;                                   // u colocated in pad slot
        *(uint4*)(g_hu2h + (size_t)gid * 8) = pack8(e8);
        g_t1[gid] = tt * LOG2E;
    }
}

// ---------------- phase 1, layer 2: 8-lane group per edge, 1 lane/row ------
// node rows carry u in slot 7 -> acc[7] accumulates usum automatically.
__global__ void k_phase1_l2(const int* __restrict__ node_idx, const float* __restrict__ a2hi)
{
    int gid = (blockIdx.x * blockDim.x + threadIdx.x) >> 3;
    if (gid >= N_EDGES) return;
    const int ll = threadIdx.x & 7;
    int s = __ldg(g_eoff + gid), epos = __ldg(g_eoff + gid + 1);

    float acc[8];
#pragma unroll
    for (int k = 0; k < 8; k++) acc[k] = 0.f;

    for (int i = s + ll; i < epos; i += 8) {
        int nd = __ldg(node_idx + i);
        uint4 v = *(const uint4*)(g_hu2h + (size_t)nd * 8);
        add8(v, acc);
    }
#pragma unroll
    for (int o = 4; o >= 1; o >>= 1)
#pragma unroll
        for (int k = 0; k < 8; k++)
            acc[k] += __shfl_down_sync(FULLM, acc[k], o, 8);

    if (ll == 0) {
        float inv = 1.f / (acc[7] + 1e-9f);          // acc[7] = sum of u
        float e8[8];
        float t2 = 0.f;
#pragma unroll
        for (int k = 0; k < 7; k++) {
            e8[k] = acc[k] * inv;
            t2 += e8[k] * __ldg(a2hi + k);
        }
        e8[7] = t2 * LOG2E;                           // t2 colocated in pad slot
        *(uint4*)(g_e2h + (size_t)gid * 8) = pack8(e8);
    }
}

// ---------------- phase 2, layer 2 + fused log_softmax ---------------------
// edge rows carry t2*log2e in slot 7 -> single 16B load per incidence.
__global__ void k_phase2_l2(float* __restrict__ H2out, float* __restrict__ logp)
{
    int gid = (blockIdx.x * blockDim.x + threadIdx.x) >> 3;
    if (gid >= N_NODES) return;
    const int ll = threadIdx.x & 7;
    int s = __ldg(g_noff + gid), e = __ldg(g_noff + gid + 1);
    float t1n = __ldg(g_t1 + gid);

    float acc[8];
#pragma unroll
    for (int k = 0; k < 8; k++) acc[k] = 0.f;
    float wsum = 0.f;

    for (int i = s + ll; i < e; i += 8) {
        int ed = __ldg(g_pedge + i);
        uint4 v = *(const uint4*)(g_e2h + (size_t)ed * 8);
        float t2 = __half2float(((const __half*)&v.w)[1]);    // slot 7
        float wv = exp2f(lrelu(t1n + t2));
        wsum += wv;
        acc8(v, acc, wv);
    }
#pragma unroll
    for (int o = 4; o >= 1; o >>= 1) {
#pragma unroll
        for (int k = 0; k < 7; k++)
            acc[k] += __shfl_down_sync(FULLM, acc[k], o, 8);
        wsum += __shfl_down_sync(FULLM, wsum, o, 8);
    }

    if (ll == 0) {
        float inv = 1.f / (wsum + 1e-9f);
        float v[N_CLS];
        float m = -1e30f;
#pragma unroll
        for (int k = 0; k < N_CLS; k++) {
            v[k] = acc[k] * inv;
            m = fmaxf(m, v[k]);
        }
        float sx = 0.f;
#pragma unroll
        for (int k = 0; k < N_CLS; k++) sx += __expf(v[k] - m);
        float ls = m + __logf(sx);
        float* h2p = H2out + (size_t)gid * N_CLS;
        float* lpp = logp + (size_t)gid * N_CLS;
#pragma unroll
        for (int k = 0; k < N_CLS; k++) {
            h2p[k] = v[k];
            lpp[k] = v[k] - ls;
        }
    }
}

// ---------------- launch ---------------------------------------------------
extern "C" void kernel_launch(void* const* d_in, const int* in_sizes, int n_in,
                              void* d_out, int out_size)
{
    const float* H   = (const float*)d_in[0];
    const float* W1  = (const float*)d_in[1];
    const float* a11 = (const float*)d_in[2];
    const float* a21 = (const float*)d_in[3];
    const float* W2  = (const float*)d_in[4];
    const float* a12 = (const float*)d_in[5];
    const float* a22 = (const float*)d_in[6];
    const int* node_idx = (const int*)d_in[7];
    const int* edge_idx = (const int*)d_in[8];

    float* out  = (float*)d_out;
    float* logp = out;                                              // [N, 7]
    float* H1   = out + (size_t)N_NODES * N_CLS;                    // [N, 16]
    float* H2   = out + (size_t)N_NODES * (N_CLS + D_HID);          // [N, 7]

    static cudaStream_t s1 = nullptr;
    static cudaEvent_t evF = nullptr, evJ = nullptr;
    static void* cnt_ptr = nullptr;
    if (s1 == nullptr) {
        cudaStreamCreateWithFlags(&s1, cudaStreamNonBlocking);
        cudaEventCreateWithFlags(&evF, cudaEventDisableTiming);
        cudaEventCreateWithFlags(&evJ, cudaEventDisableTiming);
        cudaGetSymbolAddress(&cnt_ptr, g_cnt);
    }

    // fork
    cudaEventRecord(evF, 0);
    cudaStreamWaitEvent(s1, evF, 0);

    k_eoff<<<(N_EDGES + 255) / 256, 256>>>(edge_idx);

    cudaMemsetAsync(cnt_ptr, 0, N_NODES * sizeof(int), s1);
    k_count<<<(NNZ / 4 + 255) / 256, 256, 0, s1>>>((const int4*)node_idx);
    k_scan1<<<100, 1024, 0, s1>>>();
    k_scan2<<<1, 128, 0, s1>>>();
    k_scan3<<<100, 1024, 0, s1>>>();

    k_gemm1<<<(N_NODES + 127) / 128, 128>>>(H, W1, a11, a21);

    k_scatter<<<(NNZ / 4 + 255) / 256, 256, 0, s1>>>((const int4*)node_idx,
                                                     (const int4*)edge_idx);
    cudaEventRecord(evJ, s1);

    // 8-lane groups: 32 segments per 256-thread block
    k_phase1_l1<<<N_EDGES / 32, 256>>>(node_idx, a21 + D_HID);

    cudaStreamWaitEvent(0, evJ, 0);

    k_phase2_l1<<<N_NODES / 32, 256>>>(H1, W2, a12, a22);
    k_phase1_l2<<<N_EDGES / 32, 256>>>(node_idx, a22 + N_CLS);
    k_phase2_l2<<<N_NODES / 32, 256>>>(H2, logp);
}